// round 4
// baseline (speedup 1.0000x reference)
#include <cuda_runtime.h>
#include <math.h>

#define NN   8192
#define EE   131072
#define IND  3000
#define H1D  256
#define H2D  64

typedef unsigned long long u64;

// ---------------- scratch ----------------
__device__ float g_XW   [NN*H1D];   // gene_data @ W1
__device__ float g_H1   [NN*H1D];   // relu(conv1) clean
__device__ float g_H1c  [NN*H1D];   // relu(conv1) corrupted
__device__ float g_XW2  [NN*H2D];
__device__ float g_XW2c [NN*H2D];
__device__ float g_X2c  [NN*H2D];
__device__ float g_G1   [NN*H2D];
__device__ float g_G1c  [NN*H2D];
__device__ float g_dinv [NN];
__device__ int   g_deg  [NN];
__device__ int   g_off  [NN+1];
__device__ int   g_fill [NN];
__device__ int   g_permI[NN];
__device__ int   g_csr_src [EE];
__device__ int   g_csr_psrc[EE];
__device__ float g_csr_nm  [EE];
__device__ int   g_is64;

// ---------------- packed fp32x2 helpers ----------------
__device__ __forceinline__ u64 pack2(float x) {
    u64 r; asm("mov.b64 %0, {%1, %1};" : "=l"(r) : "f"(x)); return r;
}
__device__ __forceinline__ void fma2(u64& d, u64 a, u64 b) {
    asm("fma.rn.f32x2 %0, %1, %2, %0;" : "+l"(d) : "l"(a), "l"(b));
}

__device__ __forceinline__ int idx_at(const void* p, int i, int is64) {
    return is64 ? (int)((const long long*)p)[i] : ((const int*)p)[i];
}

// ---------------- setup ----------------
__global__ void k_init0() {
    int i = blockIdx.x * blockDim.x + threadIdx.x;
    if (i < NN) g_deg[i] = 1;               // self loop
    if (i == 0) g_is64 = 1;
}

// int32 vs int64 detection: int32 data read as int64 is out of [0,NN) w.h.p.
// All violating threads plain-store 0 (race-free: single value).
__global__ void k_detect(const void* edges) {
    int i = blockIdx.x * blockDim.x + threadIdx.x;
    const long long* p = (const long long*)edges;
    long long v = p[i];
    if (v < 0 || v >= NN) g_is64 = 0;
}

__global__ void k_perm_int(const void* permp) {
    int i = blockIdx.x * blockDim.x + threadIdx.x;
    if (i < NN) g_permI[i] = idx_at(permp, i, g_is64);
}

__global__ void k_deg_count(const void* edges) {
    int e = blockIdx.x * blockDim.x + threadIdx.x;
    if (e >= EE) return;
    atomicAdd(&g_deg[idx_at(edges, EE + e, g_is64)], 1);
}
__global__ void k_dinv() {
    int i = blockIdx.x * blockDim.x + threadIdx.x;
    if (i < NN) g_dinv[i] = rsqrtf((float)g_deg[i]);
}

// ---------------- CSR offsets: single-block scan over 8192 rows ----
__global__ void k_scan() {
    __shared__ int partial[256];
    int t = threadIdx.x;
    int base = t * 32;
    int local[32];
    int sum = 0;
#pragma unroll
    for (int j = 0; j < 32; j++) {
        int c = g_deg[base + j] - 1;
        local[j] = sum;
        sum += c;
    }
    partial[t] = sum;
    __syncthreads();
    for (int o = 1; o < 256; o <<= 1) {
        int u = (t >= o) ? partial[t - o] : 0;
        __syncthreads();
        partial[t] += u;
        __syncthreads();
    }
    int off0 = partial[t] - sum;
#pragma unroll
    for (int j = 0; j < 32; j++) {
        int o = off0 + local[j];
        g_off[base + j]  = o;
        g_fill[base + j] = o;
    }
    if (t == 255) g_off[NN] = partial[255];
}

__global__ void k_fill(const void* edges) {
    int e = blockIdx.x * blockDim.x + threadIdx.x;
    if (e >= EE) return;
    int is64 = g_is64;
    int s = idx_at(edges, e, is64);
    int d = idx_at(edges, EE + e, is64);
    int pos = atomicAdd(&g_fill[d], 1);
    g_csr_src [pos] = s;
    g_csr_psrc[pos] = g_permI[s];
    g_csr_nm  [pos] = g_dinv[s] * g_dinv[d];
}

// ---------------- GEMM1: [8192,3000]@[3000,256], f32x2 pipes --------
// 128x128 tile, BK=8, 256 threads, 8x8 microtile (packed as 8x4 f32x2).
__global__ void __launch_bounds__(256, 1)
k_gemm1(const float* __restrict__ A, const float* __restrict__ B) {
    __shared__ float As[2][8][128];
    __shared__ float Bs[2][8][128];
    int tid = threadIdx.x;
    int m0 = blockIdx.y * 128;
    int n0 = blockIdx.x * 128;
    int ty = tid >> 4, tx = tid & 15;
    int ar = tid >> 1, ak = (tid & 1) * 4;
    int br = tid >> 5, bc = (tid & 31) * 4;
    const float* Aptr = A + (size_t)(m0 + ar) * IND + ak;
    const float* Bptr = B + (size_t)br * H1D + n0 + bc;

    u64 acc[8][4];
#pragma unroll
    for (int i = 0; i < 8; i++)
#pragma unroll
        for (int j = 0; j < 4; j++) acc[i][j] = 0ull;

    float4 a0 = *(const float4*)Aptr;
    float4 b0 = *(const float4*)Bptr;
    As[0][ak+0][ar] = a0.x; As[0][ak+1][ar] = a0.y;
    As[0][ak+2][ar] = a0.z; As[0][ak+3][ar] = a0.w;
    *(float4*)&Bs[0][br][bc] = b0;
    __syncthreads();

    int buf = 0;
    for (int k0 = 8; k0 < IND; k0 += 8) {
        float4 an = *(const float4*)(Aptr + k0);
        float4 bn = *(const float4*)(Bptr + (size_t)k0 * H1D);
#pragma unroll
        for (int kk = 0; kk < 8; kk++) {
            float ra[8];
            *(float4*)&ra[0] = *(const float4*)&As[buf][kk][ty*8];
            *(float4*)&ra[4] = *(const float4*)&As[buf][kk][ty*8+4];
            ulonglong2 rb01 = *(const ulonglong2*)&Bs[buf][kk][tx*8];
            ulonglong2 rb23 = *(const ulonglong2*)&Bs[buf][kk][tx*8+4];
#pragma unroll
            for (int i = 0; i < 8; i++) {
                u64 aa = pack2(ra[i]);
                fma2(acc[i][0], aa, rb01.x);
                fma2(acc[i][1], aa, rb01.y);
                fma2(acc[i][2], aa, rb23.x);
                fma2(acc[i][3], aa, rb23.y);
            }
        }
        buf ^= 1;
        As[buf][ak+0][ar] = an.x; As[buf][ak+1][ar] = an.y;
        As[buf][ak+2][ar] = an.z; As[buf][ak+3][ar] = an.w;
        *(float4*)&Bs[buf][br][bc] = bn;
        __syncthreads();
    }
#pragma unroll
    for (int kk = 0; kk < 8; kk++) {
        float ra[8];
        *(float4*)&ra[0] = *(const float4*)&As[buf][kk][ty*8];
        *(float4*)&ra[4] = *(const float4*)&As[buf][kk][ty*8+4];
        ulonglong2 rb01 = *(const ulonglong2*)&Bs[buf][kk][tx*8];
        ulonglong2 rb23 = *(const ulonglong2*)&Bs[buf][kk][tx*8+4];
#pragma unroll
        for (int i = 0; i < 8; i++) {
            u64 aa = pack2(ra[i]);
            fma2(acc[i][0], aa, rb01.x);
            fma2(acc[i][1], aa, rb01.y);
            fma2(acc[i][2], aa, rb23.x);
            fma2(acc[i][3], aa, rb23.y);
        }
    }

#pragma unroll
    for (int i = 0; i < 8; i++) {
        float* o = &g_XW[(size_t)(m0 + ty*8 + i) * H1D + n0 + tx*8];
        ulonglong2 v01; v01.x = acc[i][0]; v01.y = acc[i][1];
        ulonglong2 v23; v23.x = acc[i][2]; v23.y = acc[i][3];
        *(ulonglong2*)o       = v01;
        *(ulonglong2*)(o + 4) = v23;
    }
}

// ---------------- conv1 gather (fused self term + bias + relu) -----
__global__ void k_gather1(const float* __restrict__ b1) {
    int i = blockIdx.x;
    int f = threadIdx.x;            // 256 = H1D
    float s2 = g_dinv[i] * g_dinv[i];
    int pi = g_permI[i];
    float acc  = s2 * g_XW[(size_t)i  * H1D + f];
    float accc = s2 * g_XW[(size_t)pi * H1D + f];
    int e1 = g_off[i + 1];
    for (int e = g_off[i]; e < e1; e++) {
        int s  = g_csr_src[e];
        int ps = g_csr_psrc[e];
        float nm = g_csr_nm[e];
        acc  += nm * g_XW[(size_t)s  * H1D + f];
        accc += nm * g_XW[(size_t)ps * H1D + f];
    }
    float bb = b1[f];
    float v = acc + bb;
    g_H1 [(size_t)i * H1D + f] = v > 0.f ? v : 0.f;
    v = accc + bb;
    g_H1c[(size_t)i * H1D + f] = v > 0.f ? v : 0.f;
}

// ---------------- GEMM2: [2*8192,256]@[256,64], register-tiled ------
// 128 blocks; block bx<64 -> g_H1 rows, else g_H1c. Tile 128x64, BK=8.
__global__ void __launch_bounds__(256, 1)
k_gemm2(const float* __restrict__ W2) {
    const float* Am = (blockIdx.x < 64) ? g_H1  : g_H1c;
    float*       Om = (blockIdx.x < 64) ? g_XW2 : g_XW2c;
    int m0 = (blockIdx.x & 63) * 128;

    __shared__ float As[2][8][128];
    __shared__ float Bs[2][8][64];
    int tid = threadIdx.x;
    int ty = tid >> 4, tx = tid & 15;
    int ar = tid >> 1, ak = (tid & 1) * 4;
    int br = tid >> 5, bc = (tid & 31) * 2;
    const float* Aptr = Am + (size_t)(m0 + ar) * H1D + ak;
    const float* Bptr = W2 + (size_t)br * H2D + bc;

    u64 acc[8][2];
#pragma unroll
    for (int i = 0; i < 8; i++) { acc[i][0] = 0ull; acc[i][1] = 0ull; }

    float4 a0 = *(const float4*)Aptr;
    float2 b0 = *(const float2*)Bptr;
    As[0][ak+0][ar] = a0.x; As[0][ak+1][ar] = a0.y;
    As[0][ak+2][ar] = a0.z; As[0][ak+3][ar] = a0.w;
    *(float2*)&Bs[0][br][bc] = b0;
    __syncthreads();

    int buf = 0;
    for (int k0 = 8; k0 < H1D; k0 += 8) {
        float4 an = *(const float4*)(Aptr + k0);
        float2 bn = *(const float2*)(Bptr + (size_t)k0 * H2D);
#pragma unroll
        for (int kk = 0; kk < 8; kk++) {
            float ra[8];
            *(float4*)&ra[0] = *(const float4*)&As[buf][kk][ty*8];
            *(float4*)&ra[4] = *(const float4*)&As[buf][kk][ty*8+4];
            ulonglong2 rb = *(const ulonglong2*)&Bs[buf][kk][tx*4];
#pragma unroll
            for (int i = 0; i < 8; i++) {
                u64 aa = pack2(ra[i]);
                fma2(acc[i][0], aa, rb.x);
                fma2(acc[i][1], aa, rb.y);
            }
        }
        buf ^= 1;
        As[buf][ak+0][ar] = an.x; As[buf][ak+1][ar] = an.y;
        As[buf][ak+2][ar] = an.z; As[buf][ak+3][ar] = an.w;
        *(float2*)&Bs[buf][br][bc] = bn;
        __syncthreads();
    }
#pragma unroll
    for (int kk = 0; kk < 8; kk++) {
        float ra[8];
        *(float4*)&ra[0] = *(const float4*)&As[buf][kk][ty*8];
        *(float4*)&ra[4] = *(const float4*)&As[buf][kk][ty*8+4];
        ulonglong2 rb = *(const ulonglong2*)&Bs[buf][kk][tx*4];
#pragma unroll
        for (int i = 0; i < 8; i++) {
            u64 aa = pack2(ra[i]);
            fma2(acc[i][0], aa, rb.x);
            fma2(acc[i][1], aa, rb.y);
        }
    }

#pragma unroll
    for (int i = 0; i < 8; i++) {
        ulonglong2 v; v.x = acc[i][0]; v.y = acc[i][1];
        *(ulonglong2*)&Om[(size_t)(m0 + ty*8 + i) * H2D + tx*4] = v;
    }
}

// ---------------- conv2 gather (fused bias + relu) ------------------
__global__ void k_gather2(const float* __restrict__ b2, float* __restrict__ out_x1) {
    int t = threadIdx.x;            // 256
    int i = blockIdx.x * 4 + (t >> 6);
    int f = t & 63;
    float s2 = g_dinv[i] * g_dinv[i];
    float acc  = s2 * g_XW2 [(size_t)i * H2D + f];
    float accc = s2 * g_XW2c[(size_t)i * H2D + f];
    int e1 = g_off[i + 1];
    for (int e = g_off[i]; e < e1; e++) {
        int s = g_csr_src[e];
        float nm = g_csr_nm[e];
        acc  += nm * g_XW2 [(size_t)s * H2D + f];
        accc += nm * g_XW2c[(size_t)s * H2D + f];
    }
    float bb = b2[f];
    float v = acc + bb;
    out_x1[(size_t)i * H2D + f] = v > 0.f ? v : 0.f;
    v = accc + bb;
    g_X2c [(size_t)i * H2D + f] = v > 0.f ? v : 0.f;
}

// ---------------- masked avg readout + normalize + sigmoid ---------
__global__ void k_readout(const float* __restrict__ mask, const float* __restrict__ x1) {
    __shared__ float acc1[H2D], acc2[H2D];
    __shared__ float srs, nrm1, nrm2;
    int i = blockIdx.x;
    int tid = threadIdx.x;  // 256
    if (tid < H2D) { acc1[tid] = 0.f; acc2[tid] = 0.f; }
    if (tid == 0) srs = 0.f;
    __syncthreads();

    float rs = 0.f;
    const float4* m4 = (const float4*)&mask[(size_t)i * NN];
    for (int j4 = tid; j4 < NN / 4; j4 += blockDim.x) {
        float4 m = m4[j4];
        rs += m.x + m.y + m.z + m.w;
        int jb = j4 * 4;
        float mv[4] = {m.x, m.y, m.z, m.w};
#pragma unroll
        for (int q = 0; q < 4; q++) {
            if (mv[q] != 0.f) {
                int j = jb + q;
                const float* xr  = &x1   [(size_t)j * H2D];
                const float* xcr = &g_X2c[(size_t)j * H2D];
#pragma unroll
                for (int f = 0; f < H2D; f++) {
                    atomicAdd(&acc1[f], mv[q] * xr[f]);
                    atomicAdd(&acc2[f], mv[q] * xcr[f]);
                }
            }
        }
    }
#pragma unroll
    for (int o = 16; o; o >>= 1) rs += __shfl_down_sync(0xFFFFFFFFu, rs, o);
    if ((tid & 31) == 0) atomicAdd(&srs, rs);
    __syncthreads();

    if (tid < H2D) {
        acc1[tid] /= srs;
        acc2[tid] /= srs;
    }
    __syncthreads();
    if (tid == 0) {
        float s1 = 0.f, s2 = 0.f;
        for (int f = 0; f < H2D; f++) { s1 += acc1[f]*acc1[f]; s2 += acc2[f]*acc2[f]; }
        nrm1 = fmaxf(sqrtf(s1), 1e-12f);
        nrm2 = fmaxf(sqrtf(s2), 1e-12f);
    }
    __syncthreads();
    if (tid < H2D) {
        float v1 = acc1[tid] / nrm1;
        float v2 = acc2[tid] / nrm2;
        g_G1 [i*H2D + tid] = 1.0f / (1.0f + expf(-v1));
        g_G1c[i*H2D + tid] = 1.0f / (1.0f + expf(-v2));
    }
}

// ---------------- bilinear discriminator ----------------
__global__ void k_bilinear(const float* __restrict__ Wd, const float* __restrict__ bd,
                           const float* __restrict__ x1,
                           float* __restrict__ ret1, float* __restrict__ ret1c) {
    __shared__ float c1[H2D], c2[H2D], h[H2D], hc[H2D];
    __shared__ float red[4][H2D];
    int i = blockIdx.x;
    int k = threadIdx.x;  // 64
    c1[k] = g_G1 [i*H2D + k];
    c2[k] = g_G1c[i*H2D + k];
    h [k] = x1   [(size_t)i*H2D + k];
    hc[k] = g_X2c[(size_t)i*H2D + k];
    __syncthreads();
    float t1 = 0.f, t2 = 0.f;
    const float4* wr = (const float4*)&Wd[k * H2D];
#pragma unroll
    for (int j4 = 0; j4 < H2D / 4; j4++) {
        float4 w = wr[j4];
        t1 += w.x*c1[j4*4] + w.y*c1[j4*4+1] + w.z*c1[j4*4+2] + w.w*c1[j4*4+3];
        t2 += w.x*c2[j4*4] + w.y*c2[j4*4+1] + w.z*c2[j4*4+2] + w.w*c2[j4*4+3];
    }
    red[0][k] = h [k] * t1;
    red[1][k] = hc[k] * t1;
    red[2][k] = hc[k] * t2;
    red[3][k] = h [k] * t2;
    __syncthreads();
    if (k < 4) {
        float s = 0.f;
        for (int j = 0; j < H2D; j++) s += red[k][j];
        s += bd[0];
        if (k == 0) ret1 [i*2 + 0] = s;
        if (k == 1) ret1 [i*2 + 1] = s;
        if (k == 2) ret1c[i*2 + 0] = s;
        if (k == 3) ret1c[i*2 + 1] = s;
    }
}

// ---------------- launch ----------------
extern "C" void kernel_launch(void* const* d_in, const int* in_sizes, int n_in,
                              void* d_out, int out_size) {
    const float* gene = (const float*)d_in[0];
    const float* mask = (const float*)d_in[1];
    const float* W1   = (const float*)d_in[2];
    const float* b1   = (const float*)d_in[3];
    const float* W2   = (const float*)d_in[4];
    const float* b2   = (const float*)d_in[5];
    const float* Wd   = (const float*)d_in[6];
    const float* bd   = (const float*)d_in[7];
    const void*  edges = d_in[8];
    const void*  perm  = d_in[9];

    float* out    = (float*)d_out;
    float* out_x1 = out;
    float* out_r1 = out + NN * H2D;
    float* out_rc = out + NN * H2D + NN * 2;

    k_init0   <<<NN / 256, 256>>>();
    k_detect  <<<EE / 256, 256>>>(edges);
    k_perm_int<<<NN / 256, 256>>>(perm);

    dim3 gg1(H1D / 128, NN / 128);   // (2, 64) — launch #4: ncu profiles this
    k_gemm1   <<<gg1, 256>>>(gene, W1);

    k_deg_count<<<EE / 256, 256>>>(edges);
    k_dinv    <<<NN / 256, 256>>>();
    k_scan    <<<1, 256>>>();
    k_fill    <<<EE / 256, 256>>>(edges);

    k_gather1 <<<NN, 256>>>(b1);
    k_gemm2   <<<128, 256>>>(W2);
    k_gather2 <<<NN / 4, 256>>>(b2, out_x1);

    k_readout <<<NN, 256>>>(mask, out_x1);
    k_bilinear<<<NN, 64>>>(Wd, bd, out_x1, out_r1, out_rc);
}

// round 5
// speedup vs baseline: 1.0050x; 1.0050x over previous
#include <cuda_runtime.h>
#include <math.h>

#define NN   8192
#define EE   131072
#define IND  3000
#define H1D  256
#define H2D  64

typedef unsigned long long u64;

// ---------------- scratch ----------------
__device__ float g_XW   [NN*H1D];   // gene_data @ W1
__device__ float g_H1   [NN*H1D];   // relu(conv1) clean
__device__ float g_H1c  [NN*H1D];   // relu(conv1) corrupted
__device__ float g_XW2  [NN*H2D];
__device__ float g_XW2c [NN*H2D];
__device__ float g_X2c  [NN*H2D];
__device__ float g_G1   [NN*H2D];
__device__ float g_G1c  [NN*H2D];
__device__ float g_dinv [NN];
__device__ int   g_deg  [NN];
__device__ int   g_off  [NN+1];
__device__ int   g_fill [NN];
__device__ int   g_permI[NN];
__device__ int   g_csr_src [EE];
__device__ int   g_csr_psrc[EE];
__device__ float g_csr_nm  [EE];
__device__ int   g_is64;

// ---------------- packed fp32x2 helpers ----------------
__device__ __forceinline__ u64 pack2(float x) {
    u64 r; asm("mov.b64 %0, {%1, %1};" : "=l"(r) : "f"(x)); return r;
}
__device__ __forceinline__ void fma2(u64& d, u64 a, u64 b) {
    asm("fma.rn.f32x2 %0, %1, %2, %0;" : "+l"(d) : "l"(a), "l"(b));
}

__device__ __forceinline__ int idx_at(const void* p, int i, int is64) {
    return is64 ? (int)((const long long*)p)[i] : ((const int*)p)[i];
}

// ---------------- setup ----------------
__global__ void k_init0() {
    int i = blockIdx.x * blockDim.x + threadIdx.x;
    if (i < NN) g_deg[i] = 1;               // self loop
    if (i == 0) g_is64 = 1;
}

// int32 vs int64 detection: int32 data read as int64 is out of [0,NN) w.h.p.
// All violating threads plain-store 0 (race-free: single value).
__global__ void k_detect(const void* edges) {
    int i = blockIdx.x * blockDim.x + threadIdx.x;
    const long long* p = (const long long*)edges;
    long long v = p[i];
    if (v < 0 || v >= NN) g_is64 = 0;
}

__global__ void k_perm_int(const void* permp) {
    int i = blockIdx.x * blockDim.x + threadIdx.x;
    if (i < NN) g_permI[i] = idx_at(permp, i, g_is64);
}

__global__ void k_deg_count(const void* edges) {
    int e = blockIdx.x * blockDim.x + threadIdx.x;
    if (e >= EE) return;
    atomicAdd(&g_deg[idx_at(edges, EE + e, g_is64)], 1);
}
__global__ void k_dinv() {
    int i = blockIdx.x * blockDim.x + threadIdx.x;
    if (i < NN) g_dinv[i] = rsqrtf((float)g_deg[i]);
}

// ---------------- CSR offsets: single-block scan over 8192 rows ----
__global__ void k_scan() {
    __shared__ int partial[256];
    int t = threadIdx.x;
    int base = t * 32;
    int local[32];
    int sum = 0;
#pragma unroll
    for (int j = 0; j < 32; j++) {
        int c = g_deg[base + j] - 1;
        local[j] = sum;
        sum += c;
    }
    partial[t] = sum;
    __syncthreads();
    for (int o = 1; o < 256; o <<= 1) {
        int u = (t >= o) ? partial[t - o] : 0;
        __syncthreads();
        partial[t] += u;
        __syncthreads();
    }
    int off0 = partial[t] - sum;
#pragma unroll
    for (int j = 0; j < 32; j++) {
        int o = off0 + local[j];
        g_off[base + j]  = o;
        g_fill[base + j] = o;
    }
    if (t == 255) g_off[NN] = partial[255];
}

__global__ void k_fill(const void* edges) {
    int e = blockIdx.x * blockDim.x + threadIdx.x;
    if (e >= EE) return;
    int is64 = g_is64;
    int s = idx_at(edges, e, is64);
    int d = idx_at(edges, EE + e, is64);
    int pos = atomicAdd(&g_fill[d], 1);
    g_csr_src [pos] = s;
    g_csr_psrc[pos] = g_permI[s];
    g_csr_nm  [pos] = g_dinv[s] * g_dinv[d];
}

// ---------------- GEMM1: [8192,3000]@[3000,256], f32x2 pipes --------
// 128x128 tile, BK=8, 256 threads, 8x8 microtile (packed as 8x4 f32x2).
__global__ void __launch_bounds__(256, 1)
k_gemm1(const float* __restrict__ A, const float* __restrict__ B) {
    __shared__ float As[2][8][128];
    __shared__ float Bs[2][8][128];
    int tid = threadIdx.x;
    int m0 = blockIdx.y * 128;
    int n0 = blockIdx.x * 128;
    int ty = tid >> 4, tx = tid & 15;
    int ar = tid >> 1, ak = (tid & 1) * 4;
    int br = tid >> 5, bc = (tid & 31) * 4;
    const float* Aptr = A + (size_t)(m0 + ar) * IND + ak;
    const float* Bptr = B + (size_t)br * H1D + n0 + bc;

    u64 acc[8][4];
#pragma unroll
    for (int i = 0; i < 8; i++)
#pragma unroll
        for (int j = 0; j < 4; j++) acc[i][j] = 0ull;

    float4 a0 = *(const float4*)Aptr;
    float4 b0 = *(const float4*)Bptr;
    As[0][ak+0][ar] = a0.x; As[0][ak+1][ar] = a0.y;
    As[0][ak+2][ar] = a0.z; As[0][ak+3][ar] = a0.w;
    *(float4*)&Bs[0][br][bc] = b0;
    __syncthreads();

    int buf = 0;
    for (int k0 = 8; k0 < IND; k0 += 8) {
        float4 an = *(const float4*)(Aptr + k0);
        float4 bn = *(const float4*)(Bptr + (size_t)k0 * H1D);
#pragma unroll
        for (int kk = 0; kk < 8; kk++) {
            float ra[8];
            *(float4*)&ra[0] = *(const float4*)&As[buf][kk][ty*8];
            *(float4*)&ra[4] = *(const float4*)&As[buf][kk][ty*8+4];
            ulonglong2 rb01 = *(const ulonglong2*)&Bs[buf][kk][tx*8];
            ulonglong2 rb23 = *(const ulonglong2*)&Bs[buf][kk][tx*8+4];
#pragma unroll
            for (int i = 0; i < 8; i++) {
                u64 aa = pack2(ra[i]);
                fma2(acc[i][0], aa, rb01.x);
                fma2(acc[i][1], aa, rb01.y);
                fma2(acc[i][2], aa, rb23.x);
                fma2(acc[i][3], aa, rb23.y);
            }
        }
        buf ^= 1;
        As[buf][ak+0][ar] = an.x; As[buf][ak+1][ar] = an.y;
        As[buf][ak+2][ar] = an.z; As[buf][ak+3][ar] = an.w;
        *(float4*)&Bs[buf][br][bc] = bn;
        __syncthreads();
    }
#pragma unroll
    for (int kk = 0; kk < 8; kk++) {
        float ra[8];
        *(float4*)&ra[0] = *(const float4*)&As[buf][kk][ty*8];
        *(float4*)&ra[4] = *(const float4*)&As[buf][kk][ty*8+4];
        ulonglong2 rb01 = *(const ulonglong2*)&Bs[buf][kk][tx*8];
        ulonglong2 rb23 = *(const ulonglong2*)&Bs[buf][kk][tx*8+4];
#pragma unroll
        for (int i = 0; i < 8; i++) {
            u64 aa = pack2(ra[i]);
            fma2(acc[i][0], aa, rb01.x);
            fma2(acc[i][1], aa, rb01.y);
            fma2(acc[i][2], aa, rb23.x);
            fma2(acc[i][3], aa, rb23.y);
        }
    }

#pragma unroll
    for (int i = 0; i < 8; i++) {
        float* o = &g_XW[(size_t)(m0 + ty*8 + i) * H1D + n0 + tx*8];
        ulonglong2 v01; v01.x = acc[i][0]; v01.y = acc[i][1];
        ulonglong2 v23; v23.x = acc[i][2]; v23.y = acc[i][3];
        *(ulonglong2*)o       = v01;
        *(ulonglong2*)(o + 4) = v23;
    }
}

// ---------------- conv1 gather (fused self term + bias + relu) -----
__global__ void k_gather1(const float* __restrict__ b1) {
    int i = blockIdx.x;
    int f = threadIdx.x;            // 256 = H1D
    float s2 = g_dinv[i] * g_dinv[i];
    int pi = g_permI[i];
    float acc  = s2 * g_XW[(size_t)i  * H1D + f];
    float accc = s2 * g_XW[(size_t)pi * H1D + f];
    int e1 = g_off[i + 1];
    for (int e = g_off[i]; e < e1; e++) {
        int s  = g_csr_src[e];
        int ps = g_csr_psrc[e];
        float nm = g_csr_nm[e];
        acc  += nm * g_XW[(size_t)s  * H1D + f];
        accc += nm * g_XW[(size_t)ps * H1D + f];
    }
    float bb = b1[f];
    float v = acc + bb;
    g_H1 [(size_t)i * H1D + f] = v > 0.f ? v : 0.f;
    v = accc + bb;
    g_H1c[(size_t)i * H1D + f] = v > 0.f ? v : 0.f;
}

// ---------------- GEMM2: [2*8192,256]@[256,64], register-tiled ------
// 128 blocks; block bx<64 -> g_H1 rows, else g_H1c. Tile 128x64, BK=8.
__global__ void __launch_bounds__(256, 1)
k_gemm2(const float* __restrict__ W2) {
    const float* Am = (blockIdx.x < 64) ? g_H1  : g_H1c;
    float*       Om = (blockIdx.x < 64) ? g_XW2 : g_XW2c;
    int m0 = (blockIdx.x & 63) * 128;

    __shared__ float As[2][8][128];
    __shared__ float Bs[2][8][64];
    int tid = threadIdx.x;
    int ty = tid >> 4, tx = tid & 15;
    int ar = tid >> 1, ak = (tid & 1) * 4;
    int br = tid >> 5, bc = (tid & 31) * 2;
    const float* Aptr = Am + (size_t)(m0 + ar) * H1D + ak;
    const float* Bptr = W2 + (size_t)br * H2D + bc;

    u64 acc[8][2];
#pragma unroll
    for (int i = 0; i < 8; i++) { acc[i][0] = 0ull; acc[i][1] = 0ull; }

    float4 a0 = *(const float4*)Aptr;
    float2 b0 = *(const float2*)Bptr;
    As[0][ak+0][ar] = a0.x; As[0][ak+1][ar] = a0.y;
    As[0][ak+2][ar] = a0.z; As[0][ak+3][ar] = a0.w;
    *(float2*)&Bs[0][br][bc] = b0;
    __syncthreads();

    int buf = 0;
    for (int k0 = 8; k0 < H1D; k0 += 8) {
        float4 an = *(const float4*)(Aptr + k0);
        float2 bn = *(const float2*)(Bptr + (size_t)k0 * H2D);
#pragma unroll
        for (int kk = 0; kk < 8; kk++) {
            float ra[8];
            *(float4*)&ra[0] = *(const float4*)&As[buf][kk][ty*8];
            *(float4*)&ra[4] = *(const float4*)&As[buf][kk][ty*8+4];
            ulonglong2 rb = *(const ulonglong2*)&Bs[buf][kk][tx*4];
#pragma unroll
            for (int i = 0; i < 8; i++) {
                u64 aa = pack2(ra[i]);
                fma2(acc[i][0], aa, rb.x);
                fma2(acc[i][1], aa, rb.y);
            }
        }
        buf ^= 1;
        As[buf][ak+0][ar] = an.x; As[buf][ak+1][ar] = an.y;
        As[buf][ak+2][ar] = an.z; As[buf][ak+3][ar] = an.w;
        *(float2*)&Bs[buf][br][bc] = bn;
        __syncthreads();
    }
#pragma unroll
    for (int kk = 0; kk < 8; kk++) {
        float ra[8];
        *(float4*)&ra[0] = *(const float4*)&As[buf][kk][ty*8];
        *(float4*)&ra[4] = *(const float4*)&As[buf][kk][ty*8+4];
        ulonglong2 rb = *(const ulonglong2*)&Bs[buf][kk][tx*4];
#pragma unroll
        for (int i = 0; i < 8; i++) {
            u64 aa = pack2(ra[i]);
            fma2(acc[i][0], aa, rb.x);
            fma2(acc[i][1], aa, rb.y);
        }
    }

#pragma unroll
    for (int i = 0; i < 8; i++) {
        ulonglong2 v; v.x = acc[i][0]; v.y = acc[i][1];
        *(ulonglong2*)&Om[(size_t)(m0 + ty*8 + i) * H2D + tx*4] = v;
    }
}

// ---------------- conv2 gather (fused bias + relu) ------------------
__global__ void k_gather2(const float* __restrict__ b2, float* __restrict__ out_x1) {
    int t = threadIdx.x;            // 256
    int i = blockIdx.x * 4 + (t >> 6);
    int f = t & 63;
    float s2 = g_dinv[i] * g_dinv[i];
    float acc  = s2 * g_XW2 [(size_t)i * H2D + f];
    float accc = s2 * g_XW2c[(size_t)i * H2D + f];
    int e1 = g_off[i + 1];
    for (int e = g_off[i]; e < e1; e++) {
        int s = g_csr_src[e];
        float nm = g_csr_nm[e];
        acc  += nm * g_XW2 [(size_t)s * H2D + f];
        accc += nm * g_XW2c[(size_t)s * H2D + f];
    }
    float bb = b2[f];
    float v = acc + bb;
    out_x1[(size_t)i * H2D + f] = v > 0.f ? v : 0.f;
    v = accc + bb;
    g_X2c [(size_t)i * H2D + f] = v > 0.f ? v : 0.f;
}

// ---------------- masked avg readout + normalize + sigmoid ---------
__global__ void k_readout(const float* __restrict__ mask, const float* __restrict__ x1) {
    __shared__ float acc1[H2D], acc2[H2D];
    __shared__ float srs, nrm1, nrm2;
    int i = blockIdx.x;
    int tid = threadIdx.x;  // 256
    if (tid < H2D) { acc1[tid] = 0.f; acc2[tid] = 0.f; }
    if (tid == 0) srs = 0.f;
    __syncthreads();

    float rs = 0.f;
    const float4* m4 = (const float4*)&mask[(size_t)i * NN];
    for (int j4 = tid; j4 < NN / 4; j4 += blockDim.x) {
        float4 m = m4[j4];
        rs += m.x + m.y + m.z + m.w;
        int jb = j4 * 4;
        float mv[4] = {m.x, m.y, m.z, m.w};
#pragma unroll
        for (int q = 0; q < 4; q++) {
            if (mv[q] != 0.f) {
                int j = jb + q;
                const float* xr  = &x1   [(size_t)j * H2D];
                const float* xcr = &g_X2c[(size_t)j * H2D];
#pragma unroll
                for (int f = 0; f < H2D; f++) {
                    atomicAdd(&acc1[f], mv[q] * xr[f]);
                    atomicAdd(&acc2[f], mv[q] * xcr[f]);
                }
            }
        }
    }
#pragma unroll
    for (int o = 16; o; o >>= 1) rs += __shfl_down_sync(0xFFFFFFFFu, rs, o);
    if ((tid & 31) == 0) atomicAdd(&srs, rs);
    __syncthreads();

    if (tid < H2D) {
        acc1[tid] /= srs;
        acc2[tid] /= srs;
    }
    __syncthreads();
    if (tid == 0) {
        float s1 = 0.f, s2 = 0.f;
        for (int f = 0; f < H2D; f++) { s1 += acc1[f]*acc1[f]; s2 += acc2[f]*acc2[f]; }
        nrm1 = fmaxf(sqrtf(s1), 1e-12f);
        nrm2 = fmaxf(sqrtf(s2), 1e-12f);
    }
    __syncthreads();
    if (tid < H2D) {
        float v1 = acc1[tid] / nrm1;
        float v2 = acc2[tid] / nrm2;
        g_G1 [i*H2D + tid] = 1.0f / (1.0f + expf(-v1));
        g_G1c[i*H2D + tid] = 1.0f / (1.0f + expf(-v2));
    }
}

// ---------------- bilinear discriminator ----------------
__global__ void k_bilinear(const float* __restrict__ Wd, const float* __restrict__ bd,
                           const float* __restrict__ x1,
                           float* __restrict__ ret1, float* __restrict__ ret1c) {
    __shared__ float c1[H2D], c2[H2D], h[H2D], hc[H2D];
    __shared__ float red[4][H2D];
    int i = blockIdx.x;
    int k = threadIdx.x;  // 64
    c1[k] = g_G1 [i*H2D + k];
    c2[k] = g_G1c[i*H2D + k];
    h [k] = x1   [(size_t)i*H2D + k];
    hc[k] = g_X2c[(size_t)i*H2D + k];
    __syncthreads();
    float t1 = 0.f, t2 = 0.f;
    const float4* wr = (const float4*)&Wd[k * H2D];
#pragma unroll
    for (int j4 = 0; j4 < H2D / 4; j4++) {
        float4 w = wr[j4];
        t1 += w.x*c1[j4*4] + w.y*c1[j4*4+1] + w.z*c1[j4*4+2] + w.w*c1[j4*4+3];
        t2 += w.x*c2[j4*4] + w.y*c2[j4*4+1] + w.z*c2[j4*4+2] + w.w*c2[j4*4+3];
    }
    red[0][k] = h [k] * t1;
    red[1][k] = hc[k] * t1;
    red[2][k] = hc[k] * t2;
    red[3][k] = h [k] * t2;
    __syncthreads();
    if (k < 4) {
        float s = 0.f;
        for (int j = 0; j < H2D; j++) s += red[k][j];
        s += bd[0];
        if (k == 0) ret1 [i*2 + 0] = s;
        if (k == 1) ret1 [i*2 + 1] = s;
        if (k == 2) ret1c[i*2 + 0] = s;
        if (k == 3) ret1c[i*2 + 1] = s;
    }
}

// ---------------- launch ----------------
extern "C" void kernel_launch(void* const* d_in, const int* in_sizes, int n_in,
                              void* d_out, int out_size) {
    const float* gene = (const float*)d_in[0];
    const float* mask = (const float*)d_in[1];
    const float* W1   = (const float*)d_in[2];
    const float* b1   = (const float*)d_in[3];
    const float* W2   = (const float*)d_in[4];
    const float* b2   = (const float*)d_in[5];
    const float* Wd   = (const float*)d_in[6];
    const float* bd   = (const float*)d_in[7];
    const void*  edges = d_in[8];
    const void*  perm  = d_in[9];

    float* out    = (float*)d_out;
    float* out_x1 = out;
    float* out_r1 = out + NN * H2D;
    float* out_rc = out + NN * H2D + NN * 2;

    k_init0   <<<NN / 256, 256>>>();
    k_detect  <<<EE / 256, 256>>>(edges);
    k_perm_int<<<NN / 256, 256>>>(perm);

    dim3 gg1(H1D / 128, NN / 128);   // (2, 64) — launch #4: ncu profiles this
    k_gemm1   <<<gg1, 256>>>(gene, W1);

    k_deg_count<<<EE / 256, 256>>>(edges);
    k_dinv    <<<NN / 256, 256>>>();
    k_scan    <<<1, 256>>>();
    k_fill    <<<EE / 256, 256>>>(edges);

    k_gather1 <<<NN, 256>>>(b1);
    k_gemm2   <<<128, 256>>>(W2);
    k_gather2 <<<NN / 4, 256>>>(b2, out_x1);

    k_readout <<<NN, 256>>>(mask, out_x1);
    k_bilinear<<<NN, 64>>>(Wd, bd, out_x1, out_r1, out_rc);
}

// round 6
// speedup vs baseline: 1.0074x; 1.0024x over previous
#include <cuda_runtime.h>
#include <math.h>

#define NN   8192
#define EE   131072
#define IND  3000
#define H1D  256
#define H2D  64

typedef unsigned long long u64;

// ---------------- scratch ----------------
__device__ float g_XW   [NN*H1D];   // gene_data @ W1
__device__ float g_H1   [NN*H1D];   // relu(conv1) clean
__device__ float g_H1c  [NN*H1D];   // relu(conv1) corrupted
__device__ float g_XW2  [NN*H2D];
__device__ float g_XW2c [NN*H2D];
__device__ float g_X2c  [NN*H2D];
__device__ float g_G1   [NN*H2D];
__device__ float g_G1c  [NN*H2D];
__device__ float g_dinv [NN];
__device__ int   g_deg  [NN];
__device__ int   g_off  [NN+1];
__device__ int   g_fill [NN];
__device__ int   g_permI[NN];
__device__ int   g_csr_src [EE];
__device__ int   g_csr_psrc[EE];
__device__ float g_csr_nm  [EE];
__device__ int   g_is64;

// ---------------- packed fp32x2 helpers ----------------
__device__ __forceinline__ u64 pack2(float x) {
    u64 r; asm("mov.b64 %0, {%1, %1};" : "=l"(r) : "f"(x)); return r;
}
__device__ __forceinline__ void fma2(u64& d, u64 a, u64 b) {
    asm("fma.rn.f32x2 %0, %1, %2, %0;" : "+l"(d) : "l"(a), "l"(b));
}

__device__ __forceinline__ int idx_at(const void* p, int i, int is64) {
    return is64 ? (int)((const long long*)p)[i] : ((const int*)p)[i];
}

// ---------------- setup ----------------
__global__ void k_init0() {
    int i = blockIdx.x * blockDim.x + threadIdx.x;
    if (i < NN) g_deg[i] = 1;               // self loop
    if (i == 0) g_is64 = 1;
}

// int32 vs int64 detection: int32 data read as int64 is out of [0,NN) w.h.p.
// All violating threads plain-store 0 (race-free: single value).
__global__ void k_detect(const void* edges) {
    int i = blockIdx.x * blockDim.x + threadIdx.x;
    const long long* p = (const long long*)edges;
    long long v = p[i];
    if (v < 0 || v >= NN) g_is64 = 0;
}

__global__ void k_perm_int(const void* permp) {
    int i = blockIdx.x * blockDim.x + threadIdx.x;
    if (i < NN) g_permI[i] = idx_at(permp, i, g_is64);
}

__global__ void k_deg_count(const void* edges) {
    int e = blockIdx.x * blockDim.x + threadIdx.x;
    if (e >= EE) return;
    atomicAdd(&g_deg[idx_at(edges, EE + e, g_is64)], 1);
}
__global__ void k_dinv() {
    int i = blockIdx.x * blockDim.x + threadIdx.x;
    if (i < NN) g_dinv[i] = rsqrtf((float)g_deg[i]);
}

// ---------------- CSR offsets: single-block scan over 8192 rows ----
__global__ void k_scan() {
    __shared__ int partial[256];
    int t = threadIdx.x;
    int base = t * 32;
    int local[32];
    int sum = 0;
#pragma unroll
    for (int j = 0; j < 32; j++) {
        int c = g_deg[base + j] - 1;
        local[j] = sum;
        sum += c;
    }
    partial[t] = sum;
    __syncthreads();
    for (int o = 1; o < 256; o <<= 1) {
        int u = (t >= o) ? partial[t - o] : 0;
        __syncthreads();
        partial[t] += u;
        __syncthreads();
    }
    int off0 = partial[t] - sum;
#pragma unroll
    for (int j = 0; j < 32; j++) {
        int o = off0 + local[j];
        g_off[base + j]  = o;
        g_fill[base + j] = o;
    }
    if (t == 255) g_off[NN] = partial[255];
}

__global__ void k_fill(const void* edges) {
    int e = blockIdx.x * blockDim.x + threadIdx.x;
    if (e >= EE) return;
    int is64 = g_is64;
    int s = idx_at(edges, e, is64);
    int d = idx_at(edges, EE + e, is64);
    int pos = atomicAdd(&g_fill[d], 1);
    g_csr_src [pos] = s;
    g_csr_psrc[pos] = g_permI[s];
    g_csr_nm  [pos] = g_dinv[s] * g_dinv[d];
}

// ---------------- GEMM1: [8192,3000]@[3000,256], f32x2 pipes --------
// 128x128 tile, BK=8, 256 threads, 8x8 microtile (packed as 8x4 f32x2).
__global__ void __launch_bounds__(256, 1)
k_gemm1(const float* __restrict__ A, const float* __restrict__ B) {
    __shared__ float As[2][8][128];
    __shared__ float Bs[2][8][128];
    int tid = threadIdx.x;
    int m0 = blockIdx.y * 128;
    int n0 = blockIdx.x * 128;
    int ty = tid >> 4, tx = tid & 15;
    int ar = tid >> 1, ak = (tid & 1) * 4;
    int br = tid >> 5, bc = (tid & 31) * 4;
    const float* Aptr = A + (size_t)(m0 + ar) * IND + ak;
    const float* Bptr = B + (size_t)br * H1D + n0 + bc;

    u64 acc[8][4];
#pragma unroll
    for (int i = 0; i < 8; i++)
#pragma unroll
        for (int j = 0; j < 4; j++) acc[i][j] = 0ull;

    float4 a0 = *(const float4*)Aptr;
    float4 b0 = *(const float4*)Bptr;
    As[0][ak+0][ar] = a0.x; As[0][ak+1][ar] = a0.y;
    As[0][ak+2][ar] = a0.z; As[0][ak+3][ar] = a0.w;
    *(float4*)&Bs[0][br][bc] = b0;
    __syncthreads();

    int buf = 0;
    for (int k0 = 8; k0 < IND; k0 += 8) {
        float4 an = *(const float4*)(Aptr + k0);
        float4 bn = *(const float4*)(Bptr + (size_t)k0 * H1D);
#pragma unroll
        for (int kk = 0; kk < 8; kk++) {
            float ra[8];
            *(float4*)&ra[0] = *(const float4*)&As[buf][kk][ty*8];
            *(float4*)&ra[4] = *(const float4*)&As[buf][kk][ty*8+4];
            ulonglong2 rb01 = *(const ulonglong2*)&Bs[buf][kk][tx*8];
            ulonglong2 rb23 = *(const ulonglong2*)&Bs[buf][kk][tx*8+4];
#pragma unroll
            for (int i = 0; i < 8; i++) {
                u64 aa = pack2(ra[i]);
                fma2(acc[i][0], aa, rb01.x);
                fma2(acc[i][1], aa, rb01.y);
                fma2(acc[i][2], aa, rb23.x);
                fma2(acc[i][3], aa, rb23.y);
            }
        }
        buf ^= 1;
        As[buf][ak+0][ar] = an.x; As[buf][ak+1][ar] = an.y;
        As[buf][ak+2][ar] = an.z; As[buf][ak+3][ar] = an.w;
        *(float4*)&Bs[buf][br][bc] = bn;
        __syncthreads();
    }
#pragma unroll
    for (int kk = 0; kk < 8; kk++) {
        float ra[8];
        *(float4*)&ra[0] = *(const float4*)&As[buf][kk][ty*8];
        *(float4*)&ra[4] = *(const float4*)&As[buf][kk][ty*8+4];
        ulonglong2 rb01 = *(const ulonglong2*)&Bs[buf][kk][tx*8];
        ulonglong2 rb23 = *(const ulonglong2*)&Bs[buf][kk][tx*8+4];
#pragma unroll
        for (int i = 0; i < 8; i++) {
            u64 aa = pack2(ra[i]);
            fma2(acc[i][0], aa, rb01.x);
            fma2(acc[i][1], aa, rb01.y);
            fma2(acc[i][2], aa, rb23.x);
            fma2(acc[i][3], aa, rb23.y);
        }
    }

#pragma unroll
    for (int i = 0; i < 8; i++) {
        float* o = &g_XW[(size_t)(m0 + ty*8 + i) * H1D + n0 + tx*8];
        ulonglong2 v01; v01.x = acc[i][0]; v01.y = acc[i][1];
        ulonglong2 v23; v23.x = acc[i][2]; v23.y = acc[i][3];
        *(ulonglong2*)o       = v01;
        *(ulonglong2*)(o + 4) = v23;
    }
}

// ---------------- conv1 gather (fused self term + bias + relu) -----
__global__ void k_gather1(const float* __restrict__ b1) {
    int i = blockIdx.x;
    int f = threadIdx.x;            // 256 = H1D
    float s2 = g_dinv[i] * g_dinv[i];
    int pi = g_permI[i];
    float acc  = s2 * g_XW[(size_t)i  * H1D + f];
    float accc = s2 * g_XW[(size_t)pi * H1D + f];
    int e1 = g_off[i + 1];
    for (int e = g_off[i]; e < e1; e++) {
        int s  = g_csr_src[e];
        int ps = g_csr_psrc[e];
        float nm = g_csr_nm[e];
        acc  += nm * g_XW[(size_t)s  * H1D + f];
        accc += nm * g_XW[(size_t)ps * H1D + f];
    }
    float bb = b1[f];
    float v = acc + bb;
    g_H1 [(size_t)i * H1D + f] = v > 0.f ? v : 0.f;
    v = accc + bb;
    g_H1c[(size_t)i * H1D + f] = v > 0.f ? v : 0.f;
}

// ---------------- GEMM2: [2*8192,256]@[256,64], register-tiled ------
// 128 blocks; block bx<64 -> g_H1 rows, else g_H1c. Tile 128x64, BK=8.
__global__ void __launch_bounds__(256, 1)
k_gemm2(const float* __restrict__ W2) {
    const float* Am = (blockIdx.x < 64) ? g_H1  : g_H1c;
    float*       Om = (blockIdx.x < 64) ? g_XW2 : g_XW2c;
    int m0 = (blockIdx.x & 63) * 128;

    __shared__ float As[2][8][128];
    __shared__ float Bs[2][8][64];
    int tid = threadIdx.x;
    int ty = tid >> 4, tx = tid & 15;
    int ar = tid >> 1, ak = (tid & 1) * 4;
    int br = tid >> 5, bc = (tid & 31) * 2;
    const float* Aptr = Am + (size_t)(m0 + ar) * H1D + ak;
    const float* Bptr = W2 + (size_t)br * H2D + bc;

    u64 acc[8][2];
#pragma unroll
    for (int i = 0; i < 8; i++) { acc[i][0] = 0ull; acc[i][1] = 0ull; }

    float4 a0 = *(const float4*)Aptr;
    float2 b0 = *(const float2*)Bptr;
    As[0][ak+0][ar] = a0.x; As[0][ak+1][ar] = a0.y;
    As[0][ak+2][ar] = a0.z; As[0][ak+3][ar] = a0.w;
    *(float2*)&Bs[0][br][bc] = b0;
    __syncthreads();

    int buf = 0;
    for (int k0 = 8; k0 < H1D; k0 += 8) {
        float4 an = *(const float4*)(Aptr + k0);
        float2 bn = *(const float2*)(Bptr + (size_t)k0 * H2D);
#pragma unroll
        for (int kk = 0; kk < 8; kk++) {
            float ra[8];
            *(float4*)&ra[0] = *(const float4*)&As[buf][kk][ty*8];
            *(float4*)&ra[4] = *(const float4*)&As[buf][kk][ty*8+4];
            ulonglong2 rb = *(const ulonglong2*)&Bs[buf][kk][tx*4];
#pragma unroll
            for (int i = 0; i < 8; i++) {
                u64 aa = pack2(ra[i]);
                fma2(acc[i][0], aa, rb.x);
                fma2(acc[i][1], aa, rb.y);
            }
        }
        buf ^= 1;
        As[buf][ak+0][ar] = an.x; As[buf][ak+1][ar] = an.y;
        As[buf][ak+2][ar] = an.z; As[buf][ak+3][ar] = an.w;
        *(float2*)&Bs[buf][br][bc] = bn;
        __syncthreads();
    }
#pragma unroll
    for (int kk = 0; kk < 8; kk++) {
        float ra[8];
        *(float4*)&ra[0] = *(const float4*)&As[buf][kk][ty*8];
        *(float4*)&ra[4] = *(const float4*)&As[buf][kk][ty*8+4];
        ulonglong2 rb = *(const ulonglong2*)&Bs[buf][kk][tx*4];
#pragma unroll
        for (int i = 0; i < 8; i++) {
            u64 aa = pack2(ra[i]);
            fma2(acc[i][0], aa, rb.x);
            fma2(acc[i][1], aa, rb.y);
        }
    }

#pragma unroll
    for (int i = 0; i < 8; i++) {
        ulonglong2 v; v.x = acc[i][0]; v.y = acc[i][1];
        *(ulonglong2*)&Om[(size_t)(m0 + ty*8 + i) * H2D + tx*4] = v;
    }
}

// ---------------- conv2 gather (fused bias + relu) ------------------
__global__ void k_gather2(const float* __restrict__ b2, float* __restrict__ out_x1) {
    int t = threadIdx.x;            // 256
    int i = blockIdx.x * 4 + (t >> 6);
    int f = t & 63;
    float s2 = g_dinv[i] * g_dinv[i];
    float acc  = s2 * g_XW2 [(size_t)i * H2D + f];
    float accc = s2 * g_XW2c[(size_t)i * H2D + f];
    int e1 = g_off[i + 1];
    for (int e = g_off[i]; e < e1; e++) {
        int s = g_csr_src[e];
        float nm = g_csr_nm[e];
        acc  += nm * g_XW2 [(size_t)s * H2D + f];
        accc += nm * g_XW2c[(size_t)s * H2D + f];
    }
    float bb = b2[f];
    float v = acc + bb;
    out_x1[(size_t)i * H2D + f] = v > 0.f ? v : 0.f;
    v = accc + bb;
    g_X2c [(size_t)i * H2D + f] = v > 0.f ? v : 0.f;
}

// ---------------- masked avg readout + normalize + sigmoid ---------
__global__ void k_readout(const float* __restrict__ mask, const float* __restrict__ x1) {
    __shared__ float acc1[H2D], acc2[H2D];
    __shared__ float srs, nrm1, nrm2;
    int i = blockIdx.x;
    int tid = threadIdx.x;  // 256
    if (tid < H2D) { acc1[tid] = 0.f; acc2[tid] = 0.f; }
    if (tid == 0) srs = 0.f;
    __syncthreads();

    float rs = 0.f;
    const float4* m4 = (const float4*)&mask[(size_t)i * NN];
    for (int j4 = tid; j4 < NN / 4; j4 += blockDim.x) {
        float4 m = m4[j4];
        rs += m.x + m.y + m.z + m.w;
        int jb = j4 * 4;
        float mv[4] = {m.x, m.y, m.z, m.w};
#pragma unroll
        for (int q = 0; q < 4; q++) {
            if (mv[q] != 0.f) {
                int j = jb + q;
                const float* xr  = &x1   [(size_t)j * H2D];
                const float* xcr = &g_X2c[(size_t)j * H2D];
#pragma unroll
                for (int f = 0; f < H2D; f++) {
                    atomicAdd(&acc1[f], mv[q] * xr[f]);
                    atomicAdd(&acc2[f], mv[q] * xcr[f]);
                }
            }
        }
    }
#pragma unroll
    for (int o = 16; o; o >>= 1) rs += __shfl_down_sync(0xFFFFFFFFu, rs, o);
    if ((tid & 31) == 0) atomicAdd(&srs, rs);
    __syncthreads();

    if (tid < H2D) {
        acc1[tid] /= srs;
        acc2[tid] /= srs;
    }
    __syncthreads();
    if (tid == 0) {
        float s1 = 0.f, s2 = 0.f;
        for (int f = 0; f < H2D; f++) { s1 += acc1[f]*acc1[f]; s2 += acc2[f]*acc2[f]; }
        nrm1 = fmaxf(sqrtf(s1), 1e-12f);
        nrm2 = fmaxf(sqrtf(s2), 1e-12f);
    }
    __syncthreads();
    if (tid < H2D) {
        float v1 = acc1[tid] / nrm1;
        float v2 = acc2[tid] / nrm2;
        g_G1 [i*H2D + tid] = 1.0f / (1.0f + expf(-v1));
        g_G1c[i*H2D + tid] = 1.0f / (1.0f + expf(-v2));
    }
}

// ---------------- bilinear discriminator ----------------
__global__ void k_bilinear(const float* __restrict__ Wd, const float* __restrict__ bd,
                           const float* __restrict__ x1,
                           float* __restrict__ ret1, float* __restrict__ ret1c) {
    __shared__ float c1[H2D], c2[H2D], h[H2D], hc[H2D];
    __shared__ float red[4][H2D];
    int i = blockIdx.x;
    int k = threadIdx.x;  // 64
    c1[k] = g_G1 [i*H2D + k];
    c2[k] = g_G1c[i*H2D + k];
    h [k] = x1   [(size_t)i*H2D + k];
    hc[k] = g_X2c[(size_t)i*H2D + k];
    __syncthreads();
    float t1 = 0.f, t2 = 0.f;
    const float4* wr = (const float4*)&Wd[k * H2D];
#pragma unroll
    for (int j4 = 0; j4 < H2D / 4; j4++) {
        float4 w = wr[j4];
        t1 += w.x*c1[j4*4] + w.y*c1[j4*4+1] + w.z*c1[j4*4+2] + w.w*c1[j4*4+3];
        t2 += w.x*c2[j4*4] + w.y*c2[j4*4+1] + w.z*c2[j4*4+2] + w.w*c2[j4*4+3];
    }
    red[0][k] = h [k] * t1;
    red[1][k] = hc[k] * t1;
    red[2][k] = hc[k] * t2;
    red[3][k] = h [k] * t2;
    __syncthreads();
    if (k < 4) {
        float s = 0.f;
        for (int j = 0; j < H2D; j++) s += red[k][j];
        s += bd[0];
        if (k == 0) ret1 [i*2 + 0] = s;
        if (k == 1) ret1 [i*2 + 1] = s;
        if (k == 2) ret1c[i*2 + 0] = s;
        if (k == 3) ret1c[i*2 + 1] = s;
    }
}

// ---------------- launch ----------------
extern "C" void kernel_launch(void* const* d_in, const int* in_sizes, int n_in,
                              void* d_out, int out_size) {
    const float* gene = (const float*)d_in[0];
    const float* mask = (const float*)d_in[1];
    const float* W1   = (const float*)d_in[2];
    const float* b1   = (const float*)d_in[3];
    const float* W2   = (const float*)d_in[4];
    const float* b2   = (const float*)d_in[5];
    const float* Wd   = (const float*)d_in[6];
    const float* bd   = (const float*)d_in[7];
    const void*  edges = d_in[8];
    const void*  perm  = d_in[9];

    float* out    = (float*)d_out;
    float* out_x1 = out;
    float* out_r1 = out + NN * H2D;
    float* out_rc = out + NN * H2D + NN * 2;

    k_init0   <<<NN / 256, 256>>>();
    k_detect  <<<EE / 256, 256>>>(edges);
    k_perm_int<<<NN / 256, 256>>>(perm);

    dim3 gg1(H1D / 128, NN / 128);   // (2, 64) — launch #4: ncu profiles this
    k_gemm1   <<<gg1, 256>>>(gene, W1);

    k_deg_count<<<EE / 256, 256>>>(edges);
    k_dinv    <<<NN / 256, 256>>>();
    k_scan    <<<1, 256>>>();
    k_fill    <<<EE / 256, 256>>>(edges);

    k_gather1 <<<NN, 256>>>(b1);
    k_gemm2   <<<128, 256>>>(W2);
    k_gather2 <<<NN / 4, 256>>>(b2, out_x1);

    k_readout <<<NN, 256>>>(mask, out_x1);
    k_bilinear<<<NN, 64>>>(Wd, bd, out_x1, out_r1, out_rc);
}

// round 7
// speedup vs baseline: 1.5865x; 1.5749x over previous
#include <cuda_runtime.h>
#include <math.h>

#define NN   8192
#define EE   131072
#define IND  3000
#define H1D  256
#define H2D  64

typedef unsigned long long u64;

// ---------------- scratch ----------------
__device__ float g_XW   [NN*H1D];   // gene_data @ W1
__device__ float g_H1   [NN*H1D];   // relu(conv1) clean
__device__ float g_H1c  [NN*H1D];   // relu(conv1) corrupted
__device__ float g_XW2  [NN*H2D];
__device__ float g_XW2c [NN*H2D];
__device__ float g_X2c  [NN*H2D];
__device__ float g_G1   [NN*H2D];
__device__ float g_G1c  [NN*H2D];
__device__ float g_dinv [NN];
__device__ int   g_deg  [NN];
__device__ int   g_off  [NN+1];
__device__ int   g_fill [NN];
__device__ int   g_permI[NN];
__device__ int   g_csr_src [EE];
__device__ int   g_csr_psrc[EE];
__device__ float g_csr_nm  [EE];
__device__ int   g_is64;

// ---------------- packed fp32x2 helpers ----------------
__device__ __forceinline__ u64 pack2(float x) {
    u64 r; asm("mov.b64 %0, {%1, %1};" : "=l"(r) : "f"(x)); return r;
}
__device__ __forceinline__ void fma2(u64& d, u64 a, u64 b) {
    asm("fma.rn.f32x2 %0, %1, %2, %0;" : "+l"(d) : "l"(a), "l"(b));
}

__device__ __forceinline__ int idx_at(const void* p, int i, int is64) {
    return is64 ? (int)((const long long*)p)[i] : ((const int*)p)[i];
}

// ---------------- setup ----------------
__global__ void k_init0() {
    int i = blockIdx.x * blockDim.x + threadIdx.x;
    if (i < NN) g_deg[i] = 1;               // self loop
    if (i == 0) g_is64 = 1;
}

// int32 vs int64 detection: int32 data read as int64 is out of [0,NN) w.h.p.
__global__ void k_detect(const void* edges) {
    int i = blockIdx.x * blockDim.x + threadIdx.x;
    const long long* p = (const long long*)edges;
    long long v = p[i];
    if (v < 0 || v >= NN) g_is64 = 0;
}

__global__ void k_perm_int(const void* permp) {
    int i = blockIdx.x * blockDim.x + threadIdx.x;
    if (i < NN) g_permI[i] = idx_at(permp, i, g_is64);
}

__global__ void k_deg_count(const void* edges) {
    int e = blockIdx.x * blockDim.x + threadIdx.x;
    if (e >= EE) return;
    atomicAdd(&g_deg[idx_at(edges, EE + e, g_is64)], 1);
}
__global__ void k_dinv() {
    int i = blockIdx.x * blockDim.x + threadIdx.x;
    if (i < NN) g_dinv[i] = rsqrtf((float)g_deg[i]);
}

// ---------------- CSR offsets: single-block scan over 8192 rows ----
__global__ void k_scan() {
    __shared__ int partial[256];
    int t = threadIdx.x;
    int base = t * 32;
    int local[32];
    int sum = 0;
#pragma unroll
    for (int j = 0; j < 32; j++) {
        int c = g_deg[base + j] - 1;
        local[j] = sum;
        sum += c;
    }
    partial[t] = sum;
    __syncthreads();
    for (int o = 1; o < 256; o <<= 1) {
        int u = (t >= o) ? partial[t - o] : 0;
        __syncthreads();
        partial[t] += u;
        __syncthreads();
    }
    int off0 = partial[t] - sum;
#pragma unroll
    for (int j = 0; j < 32; j++) {
        int o = off0 + local[j];
        g_off[base + j]  = o;
        g_fill[base + j] = o;
    }
    if (t == 255) g_off[NN] = partial[255];
}

__global__ void k_fill(const void* edges) {
    int e = blockIdx.x * blockDim.x + threadIdx.x;
    if (e >= EE) return;
    int is64 = g_is64;
    int s = idx_at(edges, e, is64);
    int d = idx_at(edges, EE + e, is64);
    int pos = atomicAdd(&g_fill[d], 1);
    g_csr_src [pos] = s;
    g_csr_psrc[pos] = g_permI[s];
    g_csr_nm  [pos] = g_dinv[s] * g_dinv[d];
}

// ---------------- GEMM1: [8192,3000]@[3000,256], f32x2 -------------
// 64x128 tile, BK=8, 256 threads, 4x8 microtile (4x4 u64), A prepacked
// {a,a} in smem to eliminate pack MOVs. 256 CTAs, 2 CTAs/SM = 1 wave.
__global__ void __launch_bounds__(256, 2)
k_gemm1(const float* __restrict__ A, const float* __restrict__ B) {
    __shared__ u64   As[2][8][64];
    __shared__ float Bs[2][8][128];
    int tid = threadIdx.x;
    int m0 = blockIdx.y * 64;
    int n0 = blockIdx.x * 128;
    int ty = tid >> 4, tx = tid & 15;
    int ar = tid >> 2, ak = (tid & 3) * 2;
    int br = tid >> 5, bc = (tid & 31) * 4;
    const float* Aptr = A + (size_t)(m0 + ar) * IND + ak;
    const float* Bptr = B + (size_t)br * H1D + n0 + bc;

    u64 acc[4][4];
#pragma unroll
    for (int i = 0; i < 4; i++)
#pragma unroll
        for (int j = 0; j < 4; j++) acc[i][j] = 0ull;

    float2 a0 = *(const float2*)Aptr;
    float4 b0 = *(const float4*)Bptr;
    As[0][ak  ][ar] = pack2(a0.x);
    As[0][ak+1][ar] = pack2(a0.y);
    *(float4*)&Bs[0][br][bc] = b0;
    __syncthreads();

    int buf = 0;
    for (int k0 = 8; k0 < IND; k0 += 8) {
        float2 an = *(const float2*)(Aptr + k0);
        float4 bn = *(const float4*)(Bptr + (size_t)k0 * H1D);
#pragma unroll
        for (int kk = 0; kk < 8; kk++) {
            ulonglong2 ra01 = *(const ulonglong2*)&As[buf][kk][ty*4];
            ulonglong2 ra23 = *(const ulonglong2*)&As[buf][kk][ty*4+2];
            ulonglong2 rb01 = *(const ulonglong2*)&Bs[buf][kk][tx*8];
            ulonglong2 rb23 = *(const ulonglong2*)&Bs[buf][kk][tx*8+4];
            u64 ra[4] = {ra01.x, ra01.y, ra23.x, ra23.y};
            u64 rb[4] = {rb01.x, rb01.y, rb23.x, rb23.y};
#pragma unroll
            for (int i = 0; i < 4; i++)
#pragma unroll
                for (int j = 0; j < 4; j++) fma2(acc[i][j], ra[i], rb[j]);
        }
        buf ^= 1;
        As[buf][ak  ][ar] = pack2(an.x);
        As[buf][ak+1][ar] = pack2(an.y);
        *(float4*)&Bs[buf][br][bc] = bn;
        __syncthreads();
    }
#pragma unroll
    for (int kk = 0; kk < 8; kk++) {
        ulonglong2 ra01 = *(const ulonglong2*)&As[buf][kk][ty*4];
        ulonglong2 ra23 = *(const ulonglong2*)&As[buf][kk][ty*4+2];
        ulonglong2 rb01 = *(const ulonglong2*)&Bs[buf][kk][tx*8];
        ulonglong2 rb23 = *(const ulonglong2*)&Bs[buf][kk][tx*8+4];
        u64 ra[4] = {ra01.x, ra01.y, ra23.x, ra23.y};
        u64 rb[4] = {rb01.x, rb01.y, rb23.x, rb23.y};
#pragma unroll
        for (int i = 0; i < 4; i++)
#pragma unroll
            for (int j = 0; j < 4; j++) fma2(acc[i][j], ra[i], rb[j]);
    }

#pragma unroll
    for (int i = 0; i < 4; i++) {
        float* o = &g_XW[(size_t)(m0 + ty*4 + i) * H1D + n0 + tx*8];
        ulonglong2 v01; v01.x = acc[i][0]; v01.y = acc[i][1];
        ulonglong2 v23; v23.x = acc[i][2]; v23.y = acc[i][3];
        *(ulonglong2*)o       = v01;
        *(ulonglong2*)(o + 4) = v23;
    }
}

// ---------------- conv1 gather (float4, 2 rows/block) ---------------
__global__ void k_gather1(const float* __restrict__ b1) {
    int tid = threadIdx.x;            // 128
    int i = blockIdx.x * 2 + (tid >> 6);
    int l = (tid & 63) * 4;
    float s2 = g_dinv[i] * g_dinv[i];
    int pi = g_permI[i];
    float4 x0 = *(const float4*)&g_XW[(size_t)i  * H1D + l];
    float4 xp = *(const float4*)&g_XW[(size_t)pi * H1D + l];
    float4 acc  = make_float4(s2*x0.x, s2*x0.y, s2*x0.z, s2*x0.w);
    float4 accc = make_float4(s2*xp.x, s2*xp.y, s2*xp.z, s2*xp.w);
    int e1 = g_off[i + 1];
    for (int e = g_off[i]; e < e1; e++) {
        int s  = g_csr_src[e];
        int ps = g_csr_psrc[e];
        float nm = g_csr_nm[e];
        float4 xs = *(const float4*)&g_XW[(size_t)s  * H1D + l];
        float4 xq = *(const float4*)&g_XW[(size_t)ps * H1D + l];
        acc.x  += nm*xs.x; acc.y  += nm*xs.y; acc.z  += nm*xs.z; acc.w  += nm*xs.w;
        accc.x += nm*xq.x; accc.y += nm*xq.y; accc.z += nm*xq.z; accc.w += nm*xq.w;
    }
    float4 bb = *(const float4*)&b1[l];
    float4 v;
    v.x = fmaxf(acc.x + bb.x, 0.f); v.y = fmaxf(acc.y + bb.y, 0.f);
    v.z = fmaxf(acc.z + bb.z, 0.f); v.w = fmaxf(acc.w + bb.w, 0.f);
    *(float4*)&g_H1[(size_t)i * H1D + l] = v;
    v.x = fmaxf(accc.x + bb.x, 0.f); v.y = fmaxf(accc.y + bb.y, 0.f);
    v.z = fmaxf(accc.z + bb.z, 0.f); v.w = fmaxf(accc.w + bb.w, 0.f);
    *(float4*)&g_H1c[(size_t)i * H1D + l] = v;
}

// ---------------- GEMM2: [2*8192,256]@[256,64] ----------------------
__global__ void __launch_bounds__(256, 1)
k_gemm2(const float* __restrict__ W2) {
    const float* Am = (blockIdx.x < 64) ? g_H1  : g_H1c;
    float*       Om = (blockIdx.x < 64) ? g_XW2 : g_XW2c;
    int m0 = (blockIdx.x & 63) * 128;

    __shared__ float As[2][8][128];
    __shared__ float Bs[2][8][64];
    int tid = threadIdx.x;
    int ty = tid >> 4, tx = tid & 15;
    int ar = tid >> 1, ak = (tid & 1) * 4;
    int br = tid >> 5, bc = (tid & 31) * 2;
    const float* Aptr = Am + (size_t)(m0 + ar) * H1D + ak;
    const float* Bptr = W2 + (size_t)br * H2D + bc;

    u64 acc[8][2];
#pragma unroll
    for (int i = 0; i < 8; i++) { acc[i][0] = 0ull; acc[i][1] = 0ull; }

    float4 a0 = *(const float4*)Aptr;
    float2 b0 = *(const float2*)Bptr;
    As[0][ak+0][ar] = a0.x; As[0][ak+1][ar] = a0.y;
    As[0][ak+2][ar] = a0.z; As[0][ak+3][ar] = a0.w;
    *(float2*)&Bs[0][br][bc] = b0;
    __syncthreads();

    int buf = 0;
    for (int k0 = 8; k0 < H1D; k0 += 8) {
        float4 an = *(const float4*)(Aptr + k0);
        float2 bn = *(const float2*)(Bptr + (size_t)k0 * H2D);
#pragma unroll
        for (int kk = 0; kk < 8; kk++) {
            float ra[8];
            *(float4*)&ra[0] = *(const float4*)&As[buf][kk][ty*8];
            *(float4*)&ra[4] = *(const float4*)&As[buf][kk][ty*8+4];
            ulonglong2 rb = *(const ulonglong2*)&Bs[buf][kk][tx*4];
#pragma unroll
            for (int i = 0; i < 8; i++) {
                u64 aa = pack2(ra[i]);
                fma2(acc[i][0], aa, rb.x);
                fma2(acc[i][1], aa, rb.y);
            }
        }
        buf ^= 1;
        As[buf][ak+0][ar] = an.x; As[buf][ak+1][ar] = an.y;
        As[buf][ak+2][ar] = an.z; As[buf][ak+3][ar] = an.w;
        *(float2*)&Bs[buf][br][bc] = bn;
        __syncthreads();
    }
#pragma unroll
    for (int kk = 0; kk < 8; kk++) {
        float ra[8];
        *(float4*)&ra[0] = *(const float4*)&As[buf][kk][ty*8];
        *(float4*)&ra[4] = *(const float4*)&As[buf][kk][ty*8+4];
        ulonglong2 rb = *(const ulonglong2*)&Bs[buf][kk][tx*4];
#pragma unroll
        for (int i = 0; i < 8; i++) {
            u64 aa = pack2(ra[i]);
            fma2(acc[i][0], aa, rb.x);
            fma2(acc[i][1], aa, rb.y);
        }
    }

#pragma unroll
    for (int i = 0; i < 8; i++) {
        ulonglong2 v; v.x = acc[i][0]; v.y = acc[i][1];
        *(ulonglong2*)&Om[(size_t)(m0 + ty*8 + i) * H2D + tx*4] = v;
    }
}

// ---------------- conv2 gather (float4, 16 rows/block) --------------
__global__ void k_gather2(const float* __restrict__ b2, float* __restrict__ out_x1) {
    int t = threadIdx.x;            // 256
    int i = blockIdx.x * 16 + (t >> 4);
    int l = (t & 15) * 4;
    float s2 = g_dinv[i] * g_dinv[i];
    float4 x0 = *(const float4*)&g_XW2 [(size_t)i * H2D + l];
    float4 xc = *(const float4*)&g_XW2c[(size_t)i * H2D + l];
    float4 acc  = make_float4(s2*x0.x, s2*x0.y, s2*x0.z, s2*x0.w);
    float4 accc = make_float4(s2*xc.x, s2*xc.y, s2*xc.z, s2*xc.w);
    int e1 = g_off[i + 1];
    for (int e = g_off[i]; e < e1; e++) {
        int s = g_csr_src[e];
        float nm = g_csr_nm[e];
        float4 xs = *(const float4*)&g_XW2 [(size_t)s * H2D + l];
        float4 xq = *(const float4*)&g_XW2c[(size_t)s * H2D + l];
        acc.x  += nm*xs.x; acc.y  += nm*xs.y; acc.z  += nm*xs.z; acc.w  += nm*xs.w;
        accc.x += nm*xq.x; accc.y += nm*xq.y; accc.z += nm*xq.z; accc.w += nm*xq.w;
    }
    float4 bb = *(const float4*)&b2[l];
    float4 v;
    v.x = fmaxf(acc.x + bb.x, 0.f); v.y = fmaxf(acc.y + bb.y, 0.f);
    v.z = fmaxf(acc.z + bb.z, 0.f); v.w = fmaxf(acc.w + bb.w, 0.f);
    *(float4*)&out_x1[(size_t)i * H2D + l] = v;
    v.x = fmaxf(accc.x + bb.x, 0.f); v.y = fmaxf(accc.y + bb.y, 0.f);
    v.z = fmaxf(accc.z + bb.z, 0.f); v.w = fmaxf(accc.w + bb.w, 0.f);
    *(float4*)&g_X2c[(size_t)i * H2D + l] = v;
}

// ---------------- readout: compact nnz, then coalesced gather -------
__global__ void k_readout(const float* __restrict__ mask, const float* __restrict__ x1) {
    __shared__ int   s_idx[1024];
    __shared__ float s_val[1024];
    __shared__ int   s_cnt;
    __shared__ float s_rs;
    __shared__ float part1[4][H2D], part2[4][H2D];
    __shared__ float vs1[H2D], vs2[H2D];
    __shared__ float nrm1, nrm2;
    int i = blockIdx.x;
    int tid = threadIdx.x;  // 256
    if (tid == 0) { s_cnt = 0; s_rs = 0.f; }
    __syncthreads();

    // phase 1: stream mask row, compact nonzeros
    float rs = 0.f;
    const float4* m4 = (const float4*)&mask[(size_t)i * NN];
    for (int j4 = tid; j4 < NN / 4; j4 += 256) {
        float4 m = m4[j4];
        rs += m.x + m.y + m.z + m.w;
        if (m.x != 0.f) { int p = atomicAdd(&s_cnt, 1); if (p < 1024) { s_idx[p] = j4*4;   s_val[p] = m.x; } }
        if (m.y != 0.f) { int p = atomicAdd(&s_cnt, 1); if (p < 1024) { s_idx[p] = j4*4+1; s_val[p] = m.y; } }
        if (m.z != 0.f) { int p = atomicAdd(&s_cnt, 1); if (p < 1024) { s_idx[p] = j4*4+2; s_val[p] = m.z; } }
        if (m.w != 0.f) { int p = atomicAdd(&s_cnt, 1); if (p < 1024) { s_idx[p] = j4*4+3; s_val[p] = m.w; } }
    }
#pragma unroll
    for (int o = 16; o; o >>= 1) rs += __shfl_down_sync(0xFFFFFFFFu, rs, o);
    if ((tid & 31) == 0) atomicAdd(&s_rs, rs);
    __syncthreads();

    // phase 2: 4 groups x 64 features, coalesced gathers
    int cnt = s_cnt < 1024 ? s_cnt : 1024;
    int g = tid >> 6, f = tid & 63;
    float a1 = 0.f, a2 = 0.f;
    for (int e = g; e < cnt; e += 4) {
        int j = s_idx[e];
        float mv = s_val[e];
        a1 += mv * x1   [(size_t)j * H2D + f];
        a2 += mv * g_X2c[(size_t)j * H2D + f];
    }
    part1[g][f] = a1;
    part2[g][f] = a2;
    __syncthreads();

    if (tid < H2D) {
        float inv = 1.0f / s_rs;
        vs1[tid] = (part1[0][tid] + part1[1][tid] + part1[2][tid] + part1[3][tid]) * inv;
        vs2[tid] = (part2[0][tid] + part2[1][tid] + part2[2][tid] + part2[3][tid]) * inv;
    }
    __syncthreads();
    if (tid == 0) {
        float s1 = 0.f, s2 = 0.f;
        for (int q = 0; q < H2D; q++) { s1 += vs1[q]*vs1[q]; s2 += vs2[q]*vs2[q]; }
        nrm1 = fmaxf(sqrtf(s1), 1e-12f);
        nrm2 = fmaxf(sqrtf(s2), 1e-12f);
    }
    __syncthreads();
    if (tid < H2D) {
        float v1 = vs1[tid] / nrm1;
        float v2 = vs2[tid] / nrm2;
        g_G1 [i*H2D + tid] = 1.0f / (1.0f + expf(-v1));
        g_G1c[i*H2D + tid] = 1.0f / (1.0f + expf(-v2));
    }
}

// ---------------- bilinear discriminator ----------------
__global__ void k_bilinear(const float* __restrict__ Wd, const float* __restrict__ bd,
                           const float* __restrict__ x1,
                           float* __restrict__ ret1, float* __restrict__ ret1c) {
    __shared__ float c1[H2D], c2[H2D], h[H2D], hc[H2D];
    __shared__ float red[4][H2D];
    int i = blockIdx.x;
    int k = threadIdx.x;  // 64
    c1[k] = g_G1 [i*H2D + k];
    c2[k] = g_G1c[i*H2D + k];
    h [k] = x1   [(size_t)i*H2D + k];
    hc[k] = g_X2c[(size_t)i*H2D + k];
    __syncthreads();
    float t1 = 0.f, t2 = 0.f;
    const float4* wr = (const float4*)&Wd[k * H2D];
#pragma unroll
    for (int j4 = 0; j4 < H2D / 4; j4++) {
        float4 w = wr[j4];
        t1 += w.x*c1[j4*4] + w.y*c1[j4*4+1] + w.z*c1[j4*4+2] + w.w*c1[j4*4+3];
        t2 += w.x*c2[j4*4] + w.y*c2[j4*4+1] + w.z*c2[j4*4+2] + w.w*c2[j4*4+3];
    }
    red[0][k] = h [k] * t1;
    red[1][k] = hc[k] * t1;
    red[2][k] = hc[k] * t2;
    red[3][k] = h [k] * t2;
    __syncthreads();
    if (k < 4) {
        float s = 0.f;
        for (int j = 0; j < H2D; j++) s += red[k][j];
        s += bd[0];
        if (k == 0) ret1 [i*2 + 0] = s;
        if (k == 1) ret1 [i*2 + 1] = s;
        if (k == 2) ret1c[i*2 + 0] = s;
        if (k == 3) ret1c[i*2 + 1] = s;
    }
}

// ---------------- launch ----------------
extern "C" void kernel_launch(void* const* d_in, const int* in_sizes, int n_in,
                              void* d_out, int out_size) {
    const float* gene = (const float*)d_in[0];
    const float* mask = (const float*)d_in[1];
    const float* W1   = (const float*)d_in[2];
    const float* b1   = (const float*)d_in[3];
    const float* W2   = (const float*)d_in[4];
    const float* b2   = (const float*)d_in[5];
    const float* Wd   = (const float*)d_in[6];
    const float* bd   = (const float*)d_in[7];
    const void*  edges = d_in[8];
    const void*  perm  = d_in[9];

    float* out    = (float*)d_out;
    float* out_x1 = out;
    float* out_r1 = out + NN * H2D;
    float* out_rc = out + NN * H2D + NN * 2;

    k_init0   <<<NN / 256, 256>>>();
    k_detect  <<<EE / 256, 256>>>(edges);
    k_perm_int<<<NN / 256, 256>>>(perm);

    dim3 gg1(H1D / 128, NN / 64);    // (2, 128) = 256 CTAs — launch #4 (profiled)
    k_gemm1   <<<gg1, 256>>>(gene, W1);

    k_deg_count<<<EE / 256, 256>>>(edges);
    k_dinv    <<<NN / 256, 256>>>();
    k_scan    <<<1, 256>>>();
    k_fill    <<<EE / 256, 256>>>(edges);

    k_gather1 <<<NN / 2, 128>>>(b1);
    k_gemm2   <<<128, 256>>>(W2);
    k_gather2 <<<NN / 16, 256>>>(b2, out_x1);

    k_readout <<<NN, 256>>>(mask, out_x1);
    k_bilinear<<<NN, 64>>>(Wd, bd, out_x1, out_r1, out_rc);
}

// round 8
// speedup vs baseline: 2.2830x; 1.4390x over previous
#include <cuda_runtime.h>
#include <math.h>

#define NN   8192
#define EE   131072
#define IND  3000
#define H1D  256
#define H2D  64

typedef unsigned long long u64;

// ---------------- scratch ----------------
__device__ float g_XW   [NN*H1D];
__device__ float g_H1   [NN*H1D];
__device__ float g_H1c  [NN*H1D];
__device__ float g_XW2  [NN*H2D];
__device__ float g_XW2c [NN*H2D];
__device__ float g_X2c  [NN*H2D];
__device__ float g_G1   [NN*H2D];
__device__ float g_G1c  [NN*H2D];
__device__ float g_dinv [NN];
__device__ int   g_deg  [NN];
__device__ int   g_off  [NN+1];
__device__ int   g_fill [NN];
__device__ int   g_permI[NN];
__device__ int   g_csr_src [EE];
__device__ int   g_csr_psrc[EE];
__device__ float g_csr_nm  [EE];
// zero at module load; k_init0det only ever writes the SAME value for the
// same input (deterministic), so graph replays are consistent.
__device__ int   g_notI64;

// ---------------- packed fp32x2 helpers ----------------
__device__ __forceinline__ u64 pack2(float x) {
    u64 r; asm("mov.b64 %0, {%1, %1};" : "=l"(r) : "f"(x)); return r;
}
__device__ __forceinline__ void fma2(u64& d, u64 a, u64 b) {
    asm("fma.rn.f32x2 %0, %1, %2, %0;" : "+l"(d) : "l"(a), "l"(b));
}

__device__ __forceinline__ int idx_at(const void* p, int i, int is64) {
    return is64 ? (int)((const long long*)p)[i] : ((const int*)p)[i];
}

// ---------------- setup: deg init + dtype detect in one pass --------
// int32 data reinterpreted as int64 falls outside [0,NN) w.h.p.
__global__ void k_init0det(const void* edges) {
    int i = blockIdx.x * blockDim.x + threadIdx.x;   // grid covers EE
    if (i < NN) g_deg[i] = 1;                        // self loop
    const long long* p = (const long long*)edges;
    long long v = p[i];
    if (v < 0 || v >= NN) g_notI64 = 1;
}

__global__ void k_perm_int(const void* permp) {
    int i = blockIdx.x * blockDim.x + threadIdx.x;
    if (i < NN) g_permI[i] = idx_at(permp, i, !g_notI64);
}

__global__ void k_deg_count(const void* edges) {
    int e = blockIdx.x * blockDim.x + threadIdx.x;
    if (e >= EE) return;
    atomicAdd(&g_deg[idx_at(edges, EE + e, !g_notI64)], 1);
}
__global__ void k_dinv() {
    int i = blockIdx.x * blockDim.x + threadIdx.x;
    if (i < NN) g_dinv[i] = rsqrtf((float)g_deg[i]);
}

// ---------------- CSR offsets: single-block scan --------------------
__global__ void k_scan() {
    __shared__ int partial[256];
    int t = threadIdx.x;
    int base = t * 32;
    int local[32];
    int sum = 0;
#pragma unroll
    for (int j = 0; j < 32; j++) {
        int c = g_deg[base + j] - 1;
        local[j] = sum;
        sum += c;
    }
    partial[t] = sum;
    __syncthreads();
    for (int o = 1; o < 256; o <<= 1) {
        int u = (t >= o) ? partial[t - o] : 0;
        __syncthreads();
        partial[t] += u;
        __syncthreads();
    }
    int off0 = partial[t] - sum;
#pragma unroll
    for (int j = 0; j < 32; j++) {
        int o = off0 + local[j];
        g_off[base + j]  = o;
        g_fill[base + j] = o;
    }
    if (t == 255) g_off[NN] = partial[255];
}

__global__ void k_fill(const void* edges) {
    int e = blockIdx.x * blockDim.x + threadIdx.x;
    if (e >= EE) return;
    int is64 = !g_notI64;
    int s = idx_at(edges, e, is64);
    int d = idx_at(edges, EE + e, is64);
    int pos = atomicAdd(&g_fill[d], 1);
    g_csr_src [pos] = s;
    g_csr_psrc[pos] = g_permI[s];
    g_csr_nm  [pos] = g_dinv[s] * g_dinv[d];
}

// ---------------- GEMM1: [8192,3000]@[3000,256], f32x2 -------------
// 64x128 tile, BK=8, 128 threads, 8x8 microtile (8x4 u64).
// 256 CTAs, ~12KB smem, 2 CTAs/SM resident -> 16 warps/SM.
__global__ void __launch_bounds__(128, 2)
k_gemm1(const float* __restrict__ A, const float* __restrict__ B) {
    __shared__ float As[2][8][64];
    __shared__ float Bs[2][8][128];
    int tid = threadIdx.x;
    int m0 = blockIdx.y * 64;
    int n0 = blockIdx.x * 128;
    int ty = tid >> 4, tx = tid & 15;     // 8 x 16
    int ar = tid >> 1, ak = (tid & 1) * 4;  // A: 64 rows x 8k / 128 thr
    int br = tid >> 4, bc = (tid & 15) * 8; // B: 8 rows x 128 / 128 thr
    const float* Aptr = A + (size_t)(m0 + ar) * IND + ak;
    const float* Bptr = B + (size_t)br * H1D + n0 + bc;

    u64 acc[8][4];
#pragma unroll
    for (int i = 0; i < 8; i++)
#pragma unroll
        for (int j = 0; j < 4; j++) acc[i][j] = 0ull;

    float4 a0 = *(const float4*)Aptr;
    float4 b0 = *(const float4*)Bptr;
    float4 b1 = *(const float4*)(Bptr + 4);
    As[0][ak+0][ar] = a0.x; As[0][ak+1][ar] = a0.y;
    As[0][ak+2][ar] = a0.z; As[0][ak+3][ar] = a0.w;
    *(float4*)&Bs[0][br][bc]   = b0;
    *(float4*)&Bs[0][br][bc+4] = b1;
    __syncthreads();

    int buf = 0;
    for (int k0 = 8; k0 < IND; k0 += 8) {
        float4 an = *(const float4*)(Aptr + k0);
        float4 bn0 = *(const float4*)(Bptr + (size_t)k0 * H1D);
        float4 bn1 = *(const float4*)(Bptr + (size_t)k0 * H1D + 4);
#pragma unroll
        for (int kk = 0; kk < 8; kk++) {
            float ra[8];
            *(float4*)&ra[0] = *(const float4*)&As[buf][kk][ty*8];
            *(float4*)&ra[4] = *(const float4*)&As[buf][kk][ty*8+4];
            ulonglong2 rb01 = *(const ulonglong2*)&Bs[buf][kk][tx*8];
            ulonglong2 rb23 = *(const ulonglong2*)&Bs[buf][kk][tx*8+4];
#pragma unroll
            for (int i = 0; i < 8; i++) {
                u64 aa = pack2(ra[i]);
                fma2(acc[i][0], aa, rb01.x);
                fma2(acc[i][1], aa, rb01.y);
                fma2(acc[i][2], aa, rb23.x);
                fma2(acc[i][3], aa, rb23.y);
            }
        }
        buf ^= 1;
        As[buf][ak+0][ar] = an.x; As[buf][ak+1][ar] = an.y;
        As[buf][ak+2][ar] = an.z; As[buf][ak+3][ar] = an.w;
        *(float4*)&Bs[buf][br][bc]   = bn0;
        *(float4*)&Bs[buf][br][bc+4] = bn1;
        __syncthreads();
    }
#pragma unroll
    for (int kk = 0; kk < 8; kk++) {
        float ra[8];
        *(float4*)&ra[0] = *(const float4*)&As[buf][kk][ty*8];
        *(float4*)&ra[4] = *(const float4*)&As[buf][kk][ty*8+4];
        ulonglong2 rb01 = *(const ulonglong2*)&Bs[buf][kk][tx*8];
        ulonglong2 rb23 = *(const ulonglong2*)&Bs[buf][kk][tx*8+4];
#pragma unroll
        for (int i = 0; i < 8; i++) {
            u64 aa = pack2(ra[i]);
            fma2(acc[i][0], aa, rb01.x);
            fma2(acc[i][1], aa, rb01.y);
            fma2(acc[i][2], aa, rb23.x);
            fma2(acc[i][3], aa, rb23.y);
        }
    }

#pragma unroll
    for (int i = 0; i < 8; i++) {
        float* o = &g_XW[(size_t)(m0 + ty*8 + i) * H1D + n0 + tx*8];
        ulonglong2 v01; v01.x = acc[i][0]; v01.y = acc[i][1];
        ulonglong2 v23; v23.x = acc[i][2]; v23.y = acc[i][3];
        *(ulonglong2*)o       = v01;
        *(ulonglong2*)(o + 4) = v23;
    }
}

// ---------------- conv1 gather (float4, 2 rows/block) ---------------
__global__ void k_gather1(const float* __restrict__ b1) {
    int tid = threadIdx.x;            // 128
    int i = blockIdx.x * 2 + (tid >> 6);
    int l = (tid & 63) * 4;
    float s2 = g_dinv[i] * g_dinv[i];
    int pi = g_permI[i];
    float4 x0 = *(const float4*)&g_XW[(size_t)i  * H1D + l];
    float4 xp = *(const float4*)&g_XW[(size_t)pi * H1D + l];
    float4 acc  = make_float4(s2*x0.x, s2*x0.y, s2*x0.z, s2*x0.w);
    float4 accc = make_float4(s2*xp.x, s2*xp.y, s2*xp.z, s2*xp.w);
    int e1 = g_off[i + 1];
    for (int e = g_off[i]; e < e1; e++) {
        int s  = g_csr_src[e];
        int ps = g_csr_psrc[e];
        float nm = g_csr_nm[e];
        float4 xs = *(const float4*)&g_XW[(size_t)s  * H1D + l];
        float4 xq = *(const float4*)&g_XW[(size_t)ps * H1D + l];
        acc.x  += nm*xs.x; acc.y  += nm*xs.y; acc.z  += nm*xs.z; acc.w  += nm*xs.w;
        accc.x += nm*xq.x; accc.y += nm*xq.y; accc.z += nm*xq.z; accc.w += nm*xq.w;
    }
    float4 bb = *(const float4*)&b1[l];
    float4 v;
    v.x = fmaxf(acc.x + bb.x, 0.f); v.y = fmaxf(acc.y + bb.y, 0.f);
    v.z = fmaxf(acc.z + bb.z, 0.f); v.w = fmaxf(acc.w + bb.w, 0.f);
    *(float4*)&g_H1[(size_t)i * H1D + l] = v;
    v.x = fmaxf(accc.x + bb.x, 0.f); v.y = fmaxf(accc.y + bb.y, 0.f);
    v.z = fmaxf(accc.z + bb.z, 0.f); v.w = fmaxf(accc.w + bb.w, 0.f);
    *(float4*)&g_H1c[(size_t)i * H1D + l] = v;
}

// ---------------- GEMM2: [2*8192,256]@[256,64] ----------------------
__global__ void __launch_bounds__(256, 1)
k_gemm2(const float* __restrict__ W2) {
    const float* Am = (blockIdx.x < 64) ? g_H1  : g_H1c;
    float*       Om = (blockIdx.x < 64) ? g_XW2 : g_XW2c;
    int m0 = (blockIdx.x & 63) * 128;

    __shared__ float As[2][8][128];
    __shared__ float Bs[2][8][64];
    int tid = threadIdx.x;
    int ty = tid >> 4, tx = tid & 15;
    int ar = tid >> 1, ak = (tid & 1) * 4;
    int br = tid >> 5, bc = (tid & 31) * 2;
    const float* Aptr = Am + (size_t)(m0 + ar) * H1D + ak;
    const float* Bptr = W2 + (size_t)br * H2D + bc;

    u64 acc[8][2];
#pragma unroll
    for (int i = 0; i < 8; i++) { acc[i][0] = 0ull; acc[i][1] = 0ull; }

    float4 a0 = *(const float4*)Aptr;
    float2 b0 = *(const float2*)Bptr;
    As[0][ak+0][ar] = a0.x; As[0][ak+1][ar] = a0.y;
    As[0][ak+2][ar] = a0.z; As[0][ak+3][ar] = a0.w;
    *(float2*)&Bs[0][br][bc] = b0;
    __syncthreads();

    int buf = 0;
    for (int k0 = 8; k0 < H1D; k0 += 8) {
        float4 an = *(const float4*)(Aptr + k0);
        float2 bn = *(const float2*)(Bptr + (size_t)k0 * H2D);
#pragma unroll
        for (int kk = 0; kk < 8; kk++) {
            float ra[8];
            *(float4*)&ra[0] = *(const float4*)&As[buf][kk][ty*8];
            *(float4*)&ra[4] = *(const float4*)&As[buf][kk][ty*8+4];
            ulonglong2 rb = *(const ulonglong2*)&Bs[buf][kk][tx*4];
#pragma unroll
            for (int i = 0; i < 8; i++) {
                u64 aa = pack2(ra[i]);
                fma2(acc[i][0], aa, rb.x);
                fma2(acc[i][1], aa, rb.y);
            }
        }
        buf ^= 1;
        As[buf][ak+0][ar] = an.x; As[buf][ak+1][ar] = an.y;
        As[buf][ak+2][ar] = an.z; As[buf][ak+3][ar] = an.w;
        *(float2*)&Bs[buf][br][bc] = bn;
        __syncthreads();
    }
#pragma unroll
    for (int kk = 0; kk < 8; kk++) {
        float ra[8];
        *(float4*)&ra[0] = *(const float4*)&As[buf][kk][ty*8];
        *(float4*)&ra[4] = *(const float4*)&As[buf][kk][ty*8+4];
        ulonglong2 rb = *(const ulonglong2*)&Bs[buf][kk][tx*4];
#pragma unroll
        for (int i = 0; i < 8; i++) {
            u64 aa = pack2(ra[i]);
            fma2(acc[i][0], aa, rb.x);
            fma2(acc[i][1], aa, rb.y);
        }
    }

#pragma unroll
    for (int i = 0; i < 8; i++) {
        ulonglong2 v; v.x = acc[i][0]; v.y = acc[i][1];
        *(ulonglong2*)&Om[(size_t)(m0 + ty*8 + i) * H2D + tx*4] = v;
    }
}

// ---------------- conv2 gather (float4, 16 rows/block) --------------
__global__ void k_gather2(const float* __restrict__ b2, float* __restrict__ out_x1) {
    int t = threadIdx.x;            // 256
    int i = blockIdx.x * 16 + (t >> 4);
    int l = (t & 15) * 4;
    float s2 = g_dinv[i] * g_dinv[i];
    float4 x0 = *(const float4*)&g_XW2 [(size_t)i * H2D + l];
    float4 xc = *(const float4*)&g_XW2c[(size_t)i * H2D + l];
    float4 acc  = make_float4(s2*x0.x, s2*x0.y, s2*x0.z, s2*x0.w);
    float4 accc = make_float4(s2*xc.x, s2*xc.y, s2*xc.z, s2*xc.w);
    int e1 = g_off[i + 1];
    for (int e = g_off[i]; e < e1; e++) {
        int s = g_csr_src[e];
        float nm = g_csr_nm[e];
        float4 xs = *(const float4*)&g_XW2 [(size_t)s * H2D + l];
        float4 xq = *(const float4*)&g_XW2c[(size_t)s * H2D + l];
        acc.x  += nm*xs.x; acc.y  += nm*xs.y; acc.z  += nm*xs.z; acc.w  += nm*xs.w;
        accc.x += nm*xq.x; accc.y += nm*xq.y; accc.z += nm*xq.z; accc.w += nm*xq.w;
    }
    float4 bb = *(const float4*)&b2[l];
    float4 v;
    v.x = fmaxf(acc.x + bb.x, 0.f); v.y = fmaxf(acc.y + bb.y, 0.f);
    v.z = fmaxf(acc.z + bb.z, 0.f); v.w = fmaxf(acc.w + bb.w, 0.f);
    *(float4*)&out_x1[(size_t)i * H2D + l] = v;
    v.x = fmaxf(accc.x + bb.x, 0.f); v.y = fmaxf(accc.y + bb.y, 0.f);
    v.z = fmaxf(accc.z + bb.z, 0.f); v.w = fmaxf(accc.w + bb.w, 0.f);
    *(float4*)&g_X2c[(size_t)i * H2D + l] = v;
}

// ---------------- readout: compact nnz, then coalesced gather -------
__global__ void k_readout(const float* __restrict__ mask, const float* __restrict__ x1) {
    __shared__ int   s_idx[1024];
    __shared__ float s_val[1024];
    __shared__ int   s_cnt;
    __shared__ float s_rs;
    __shared__ float part1[4][H2D], part2[4][H2D];
    __shared__ float vs1[H2D], vs2[H2D];
    __shared__ float nrm1, nrm2;
    int i = blockIdx.x;
    int tid = threadIdx.x;  // 256
    if (tid == 0) { s_cnt = 0; s_rs = 0.f; }
    __syncthreads();

    float rs = 0.f;
    const float4* m4 = (const float4*)&mask[(size_t)i * NN];
    for (int j4 = tid; j4 < NN / 4; j4 += 256) {
        float4 m = m4[j4];
        rs += m.x + m.y + m.z + m.w;
        if (m.x != 0.f) { int p = atomicAdd(&s_cnt, 1); if (p < 1024) { s_idx[p] = j4*4;   s_val[p] = m.x; } }
        if (m.y != 0.f) { int p = atomicAdd(&s_cnt, 1); if (p < 1024) { s_idx[p] = j4*4+1; s_val[p] = m.y; } }
        if (m.z != 0.f) { int p = atomicAdd(&s_cnt, 1); if (p < 1024) { s_idx[p] = j4*4+2; s_val[p] = m.z; } }
        if (m.w != 0.f) { int p = atomicAdd(&s_cnt, 1); if (p < 1024) { s_idx[p] = j4*4+3; s_val[p] = m.w; } }
    }
#pragma unroll
    for (int o = 16; o; o >>= 1) rs += __shfl_down_sync(0xFFFFFFFFu, rs, o);
    if ((tid & 31) == 0) atomicAdd(&s_rs, rs);
    __syncthreads();

    int cnt = s_cnt < 1024 ? s_cnt : 1024;
    int g = tid >> 6, f = tid & 63;
    float a1 = 0.f, a2 = 0.f;
    for (int e = g; e < cnt; e += 4) {
        int j = s_idx[e];
        float mv = s_val[e];
        a1 += mv * x1   [(size_t)j * H2D + f];
        a2 += mv * g_X2c[(size_t)j * H2D + f];
    }
    part1[g][f] = a1;
    part2[g][f] = a2;
    __syncthreads();

    if (tid < H2D) {
        float inv = 1.0f / s_rs;
        vs1[tid] = (part1[0][tid] + part1[1][tid] + part1[2][tid] + part1[3][tid]) * inv;
        vs2[tid] = (part2[0][tid] + part2[1][tid] + part2[2][tid] + part2[3][tid]) * inv;
    }
    __syncthreads();
    if (tid == 0) {
        float s1 = 0.f, s2 = 0.f;
        for (int q = 0; q < H2D; q++) { s1 += vs1[q]*vs1[q]; s2 += vs2[q]*vs2[q]; }
        nrm1 = fmaxf(sqrtf(s1), 1e-12f);
        nrm2 = fmaxf(sqrtf(s2), 1e-12f);
    }
    __syncthreads();
    if (tid < H2D) {
        float v1 = vs1[tid] / nrm1;
        float v2 = vs2[tid] / nrm2;
        g_G1 [i*H2D + tid] = 1.0f / (1.0f + expf(-v1));
        g_G1c[i*H2D + tid] = 1.0f / (1.0f + expf(-v2));
    }
}

// ---------------- bilinear discriminator ----------------
__global__ void k_bilinear(const float* __restrict__ Wd, const float* __restrict__ bd,
                           const float* __restrict__ x1,
                           float* __restrict__ ret1, float* __restrict__ ret1c) {
    __shared__ float c1[H2D], c2[H2D], h[H2D], hc[H2D];
    __shared__ float red[4][H2D];
    int i = blockIdx.x;
    int k = threadIdx.x;  // 64
    c1[k] = g_G1 [i*H2D + k];
    c2[k] = g_G1c[i*H2D + k];
    h [k] = x1   [(size_t)i*H2D + k];
    hc[k] = g_X2c[(size_t)i*H2D + k];
    __syncthreads();
    float t1 = 0.f, t2 = 0.f;
    const float4* wr = (const float4*)&Wd[k * H2D];
#pragma unroll
    for (int j4 = 0; j4 < H2D / 4; j4++) {
        float4 w = wr[j4];
        t1 += w.x*c1[j4*4] + w.y*c1[j4*4+1] + w.z*c1[j4*4+2] + w.w*c1[j4*4+3];
        t2 += w.x*c2[j4*4] + w.y*c2[j4*4+1] + w.z*c2[j4*4+2] + w.w*c2[j4*4+3];
    }
    red[0][k] = h [k] * t1;
    red[1][k] = hc[k] * t1;
    red[2][k] = hc[k] * t2;
    red[3][k] = h [k] * t2;
    __syncthreads();
    if (k < 4) {
        float s = 0.f;
        for (int j = 0; j < H2D; j++) s += red[k][j];
        s += bd[0];
        if (k == 0) ret1 [i*2 + 0] = s;
        if (k == 1) ret1 [i*2 + 1] = s;
        if (k == 2) ret1c[i*2 + 0] = s;
        if (k == 3) ret1c[i*2 + 1] = s;
    }
}

// ---------------- launch ----------------
extern "C" void kernel_launch(void* const* d_in, const int* in_sizes, int n_in,
                              void* d_out, int out_size) {
    const float* gene = (const float*)d_in[0];
    const float* mask = (const float*)d_in[1];
    const float* W1   = (const float*)d_in[2];
    const float* b1   = (const float*)d_in[3];
    const float* W2   = (const float*)d_in[4];
    const float* b2   = (const float*)d_in[5];
    const float* Wd   = (const float*)d_in[6];
    const float* bd   = (const float*)d_in[7];
    const void*  edges = d_in[8];
    const void*  perm  = d_in[9];

    float* out    = (float*)d_out;
    float* out_x1 = out;
    float* out_r1 = out + NN * H2D;
    float* out_rc = out + NN * H2D + NN * 2;

    k_init0det <<<EE / 256, 256>>>(edges);
    k_perm_int <<<NN / 256, 256>>>(perm);
    k_deg_count<<<EE / 256, 256>>>(edges);

    dim3 gg1(H1D / 128, NN / 64);    // (2, 128) = 256 CTAs — launch #4 (profiled)
    k_gemm1    <<<gg1, 128>>>(gene, W1);

    k_dinv     <<<NN / 256, 256>>>();
    k_scan     <<<1, 256>>>();
    k_fill     <<<EE / 256, 256>>>(edges);

    k_gather1  <<<NN / 2, 128>>>(b1);
    k_gemm2    <<<128, 256>>>(W2);
    k_gather2  <<<NN / 16, 256>>>(b2, out_x1);

    k_readout  <<<NN, 256>>>(mask, out_x1);
    k_bilinear <<<NN, 64>>>(Wd, bd, out_x1, out_r1, out_rc);
}